// round 9
// baseline (speedup 1.0000x reference)
#include <cuda_runtime.h>
#include <math.h>

#define VV 4
#define NN 2048
#define DD 128
#define KK 10
#define NPAIR 12
#define CAP 160            // candidate key slots per row (40 chunks x 4)
#define TAU0 0.99f         // static threshold; exact fallback covers any input
#define PROJ_BLOCKS 768
#define TOPK_BLOCKS 1536   // 16 rows per block (4 warps x 4 rows)
#define TOTAL_BLOCKS (PROJ_BLOCKS + TOPK_BLOCKS)  // 2304, bid%3==0 -> proj

// ---------------- scratch (no allocs allowed) ----------------
__device__ float g_Q[VV * NN * DD];
__device__ float g_K[VV * NN * DD];
__device__ float g_V[VV * NN * DD];
__device__ int   g_idx[NPAIR * NN * KK];
__device__ float4 g_meanV4[VV * (DD / 4)];

// total-order 64-bit key: higher value wins; ties -> lower index (matches
// lax.top_k). C >= 0 so monotonic float map is bits | signbit.
__device__ __forceinline__ unsigned long long tk_key(float x, int m)
{
    unsigned int mb = __float_as_uint(x) | 0x80000000u;
    return ((unsigned long long)mb << 32) | (unsigned int)(NN - 1 - m);
}

__device__ __forceinline__ unsigned long long wmax64(unsigned long long k)
{
#pragma unroll
    for (int off = 16; off > 0; off >>= 1) {
        unsigned long long o = __shfl_xor_sync(0xffffffffu, k, off);
        if (o > k) k = o;
    }
    return k;
}

struct ProjS {
    float Xs[32][16];
    float Ws[16][132];
};
struct TopkS {
    float4 buf[4][2][512];               // 4 warps x 2 x 8 KB = 64 KB
    unsigned long long cbuf[4][CAP];     // 5 KB
};
#define DSMEM_BYTES (sizeof(TopkS))

// exact bounded-rescan fallback (rare), smem-resident row, one warp
__device__ void topk_fallback(const float4* rp4, int lane, int* outp)
{
    unsigned long long bound = ~0ull;
    for (int r = 0; r < KK; ++r) {
        unsigned long long cand = 0ull;
        for (int i = 0; i < 16; ++i) {
            float4 v = rp4[lane + (i << 5)];
            int mb = (lane + (i << 5)) << 2;
            unsigned long long k;
            k = tk_key(v.x, mb + 0); if (k < bound && k > cand) cand = k;
            k = tk_key(v.y, mb + 1); if (k < bound && k > cand) cand = k;
            k = tk_key(v.z, mb + 2); if (k < bound && k > cand) cand = k;
            k = tk_key(v.w, mb + 3); if (k < bound && k > cand) cand = k;
        }
        unsigned long long m = wmax64(cand);
        if (lane == 0) outp[r] = NN - 1 - (int)(m & 0xffffffffu);
        bound = m;
    }
}

// process one smem-resident row: threshold scan -> exact top-10
__device__ __forceinline__ void topk_process_row(
    const float4* rb, unsigned long long* cbuf, int lane, int rowg)
{
    unsigned int lmask = (1u << lane) - 1u;
    int nch = 0;
#pragma unroll
    for (int i = 0; i < 16; ++i) {
        float4 a = rb[lane + (i << 5)];
        int mb = (lane + (i << 5)) << 2;
        float ma = fmaxf(fmaxf(a.x, a.y), fmaxf(a.z, a.w));
        bool hit = (ma >= TAU0);
        unsigned int bal = __ballot_sync(0xffffffffu, hit);
        if (hit) {
            int pos = (nch + __popc(bal & lmask)) * 4;
            if (pos <= CAP - 4) {
                ulonglong2* d = (ulonglong2*)&cbuf[pos];
                d[0] = make_ulonglong2(tk_key(a.x, mb + 0), tk_key(a.y, mb + 1));
                d[1] = make_ulonglong2(tk_key(a.z, mb + 2), tk_key(a.w, mb + 3));
            }
        }
        nch += __popc(bal);
    }
    __syncwarp();

    const unsigned int tau_hi = __float_as_uint(TAU0) | 0x80000000u;
    int nslots = nch * 4;
    int* outp = g_idx + (size_t)rowg * KK;
    bool ok = (nslots <= CAP);
    if (ok) {
        unsigned long long k0 = (lane       < nslots) ? cbuf[lane]       : 0ull;
        unsigned long long k1 = (lane + 32  < nslots) ? cbuf[lane + 32]  : 0ull;
        unsigned long long k2 = (lane + 64  < nslots) ? cbuf[lane + 64]  : 0ull;
        unsigned long long k3 = (lane + 96  < nslots) ? cbuf[lane + 96]  : 0ull;
        unsigned long long k4 = (lane + 128 < nslots) ? cbuf[lane + 128] : 0ull;
        unsigned long long cand = k0;
        if (k1 > cand) cand = k1;
        if (k2 > cand) cand = k2;
        if (k3 > cand) cand = k3;
        if (k4 > cand) cand = k4;
        unsigned long long m = 0ull;
#pragma unroll
        for (int r = 0; r < KK; ++r) {
            m = wmax64(cand);
            if (lane == 0) outp[r] = NN - 1 - (int)(m & 0xffffffffu);
            if (cand == m) {                // unique keys: one winner
                if      (k0 == m) k0 = 0ull;
                else if (k1 == m) k1 = 0ull;
                else if (k2 == m) k2 = 0ull;
                else if (k3 == m) k3 = 0ull;
                else              k4 = 0ull;
                cand = k0;
                if (k1 > cand) cand = k1;
                if (k2 > cand) cand = k2;
                if (k3 > cand) cand = k3;
                if (k4 > cand) cand = k4;
            }
        }
        ok = ((unsigned int)(m >> 32) >= tau_hi);
    }
    if (!ok) topk_fallback(rb, lane, outp);
}

// ================= fused proj (+meanV) + topk =================
__global__ __launch_bounds__(128) void proj_topk_kernel(
    const float* __restrict__ aligned,
    const float* __restrict__ WQ,
    const float* __restrict__ WK,
    const float* __restrict__ WV,
    const float* __restrict__ C)
{
    extern __shared__ __align__(16) unsigned char smem_raw[];
    int bid = blockIdx.x;
    int tid = threadIdx.x;
    int warp = tid >> 5, lane = tid & 31;

    if (bid % 3 == 0) {
        // ---------------- projection GEMM: 32 rows x 128 cols ----------------
        ProjS& S = *reinterpret_cast<ProjS*>(smem_raw);
        int pb = bid / 3;                 // 0..767
        int tile = pb & 63;
        int vm   = pb >> 6;               // 0..11
        int v = vm / 3, mat = vm % 3;
        const float* W = (mat == 0 ? WQ : (mat == 1 ? WK : WV)) + (size_t)v * DD * DD;
        float* Out = (mat == 0 ? g_Q : (mat == 1 ? g_K : g_V))
                     + (size_t)v * NN * DD + (size_t)tile * 32 * DD;
        const float* X = aligned + (size_t)v * NN * DD + (size_t)tile * 32 * DD;

        float acc[8][4];
#pragma unroll
        for (int i = 0; i < 8; ++i)
#pragma unroll
            for (int c = 0; c < 4; ++c) acc[i][c] = 0.f;

        for (int d0 = 0; d0 < DD; d0 += 16) {
            {
                int r = tid >> 2, f = tid & 3;
                float4 xv = *(const float4*)(X + (size_t)r * DD + d0 + f * 4);
                *(float4*)&S.Xs[r][f * 4] = xv;
            }
#pragma unroll
            for (int j = 0; j < 4; ++j) {
                int lin = tid * 4 + j;
                int e = lin >> 2, f = lin & 3;
                float4 wv = *(const float4*)(W + (size_t)e * DD + d0 + f * 4);
                S.Ws[f * 4 + 0][e] = wv.x;
                S.Ws[f * 4 + 1][e] = wv.y;
                S.Ws[f * 4 + 2][e] = wv.z;
                S.Ws[f * 4 + 3][e] = wv.w;
            }
            __syncthreads();
#pragma unroll
            for (int dd = 0; dd < 16; ++dd) {
                float4 b = *(const float4*)&S.Ws[dd][lane * 4];
#pragma unroll
                for (int i = 0; i < 8; ++i) {
                    float a = S.Xs[warp * 8 + i][dd];
                    acc[i][0] += a * b.x;
                    acc[i][1] += a * b.y;
                    acc[i][2] += a * b.z;
                    acc[i][3] += a * b.w;
                }
            }
            __syncthreads();
        }
#pragma unroll
        for (int i = 0; i < 8; ++i) {
            float4 o = make_float4(acc[i][0], acc[i][1], acc[i][2], acc[i][3]);
            *(float4*)(Out + (size_t)(warp * 8 + i) * DD + lane * 4) = o;
        }
        if (mat == 2) {
#pragma unroll
            for (int c = 0; c < 4; ++c) {
                float s = 0.f;
#pragma unroll
                for (int i = 0; i < 8; ++i) s += acc[i][c];
                atomicAdd((float*)&g_meanV4[0] + v * DD + lane * 4 + c, s);
            }
        }
        return;
    }

    // ------- topk: warp owns 4 rows, double-buffered cp.async, no block syncs -------
    TopkS& S = *reinterpret_cast<TopkS*>(smem_raw);
    int tb = bid - bid / 3 - 1;           // 0..1535
    int rowbase = tb * 16 + warp * 4;     // 4 rows, same (p,q) pair (16 | NN)
    int pair = rowbase / NN, n0 = rowbase % NN;
    int p = pair / 3, qm = pair % 3;
    int q = qm + (qm >= p ? 1 : 0);
    const float* Crow = C + (((size_t)p * VV + q) * NN + n0) * (size_t)NN;

    // one row = one cp.async group (16 x 16B per lane, stride 32)
    auto issue_row = [&](int r, int slot) {
        const float4* src = (const float4*)(Crow + (size_t)r * NN);
#pragma unroll
        for (int i = 0; i < 16; ++i) {
            int c = lane + (i << 5);
            unsigned int sa = (unsigned int)__cvta_generic_to_shared(&S.buf[warp][slot][c]);
            asm volatile("cp.async.cg.shared.global [%0], [%1], 16;"
                         :: "r"(sa), "l"(src + c));
        }
        asm volatile("cp.async.commit_group;");
    };

    issue_row(0, 0);
    issue_row(1, 1);

#pragma unroll
    for (int r = 0; r < 4; ++r) {
        if (r < 3) asm volatile("cp.async.wait_group 1;" ::: "memory");
        else       asm volatile("cp.async.wait_group 0;" ::: "memory");
        __syncwarp();
        topk_process_row(&S.buf[warp][r & 1][0], &S.cbuf[warp][0],
                         lane, rowbase + r);
        __syncwarp();                      // select done before buffer reuse
        if (r + 2 < 4) issue_row(r + 2, r & 1);
    }
}

// ---------------- gather: one warp per (p,n), barrier-free ----------------
__global__ __launch_bounds__(256, 4) void gather_kernel(float* __restrict__ out)
{
    __shared__ float sc[8][32];
    __shared__ float smax[8][4];
    __shared__ float ssum[8][4];

    int tid = threadIdx.x;
    int w = tid >> 5, lane = tid & 31;
    int gw = blockIdx.x * 8 + w;          // 0..8191
    int p = gw >> 11, n = gw & (NN - 1);

    int sub = lane & 7, grp = lane >> 3;
    const float4* Qrow = (const float4*)g_Q + ((size_t)p * NN + n) * 32;
    float4 q4[4];
#pragma unroll
    for (int j = 0; j < 4; ++j) q4[j] = Qrow[sub + 8 * j];

    int myidx = 0;
    if (lane < 3 * KK) {
        int pr = p * 3 + lane / KK;
        myidx = g_idx[((size_t)pr * NN + n) * KK + (lane % KK)];
    }

#pragma unroll
    for (int it = 0; it < 8; ++it) {
        int t = it * 4 + grp;
        int tq = (t < 30) ? t : 29;
        int qm = tq / KK;
        int q = qm + (qm >= p ? 1 : 0);
        int m = __shfl_sync(0xffffffffu, myidx, t & 31);
        const float4* Kr = (const float4*)g_K + ((size_t)q * NN + m) * 32;
        float s = 0.f;
#pragma unroll
        for (int j = 0; j < 4; ++j) {
            float4 k4 = __ldg(Kr + sub + 8 * j);
            s += q4[j].x * k4.x + q4[j].y * k4.y + q4[j].z * k4.z + q4[j].w * k4.w;
        }
        s += __shfl_xor_sync(0xffffffffu, s, 1);
        s += __shfl_xor_sync(0xffffffffu, s, 2);
        s += __shfl_xor_sync(0xffffffffu, s, 4);
        if (sub == 0 && t < 30) sc[w][t] = s * 0.08838834764831845f;
    }
    __syncwarp();

    if (lane < 3) {
        float mx = -3.4e38f;
#pragma unroll
        for (int k = 0; k < KK; ++k) mx = fmaxf(mx, sc[w][lane * KK + k]);
        smax[w][lane] = mx;
    }
    __syncwarp();
    if (lane < 3 * KK) sc[w][lane] = expf(sc[w][lane] - smax[w][lane / KK]);
    __syncwarp();
    if (lane < 3) {
        float su = 0.f;
#pragma unroll
        for (int k = 0; k < KK; ++k) su += sc[w][lane * KK + k];
        ssum[w][lane] = su;
    }
    __syncwarp();
    float wt = (lane < 3 * KK) ? sc[w][lane] / ssum[w][lane / KK] : 0.f;

    float4 mv = g_meanV4[p * 32 + lane];
    const float inv = 1.0f / NN;
    float4 acc = make_float4(mv.x * inv, mv.y * inv, mv.z * inv, mv.w * inv);
#pragma unroll
    for (int t = 0; t < 3 * KK; ++t) {
        float wb = __shfl_sync(0xffffffffu, wt, t);
        int   mb = __shfl_sync(0xffffffffu, myidx, t);
        int qm = t / KK;
        int q = qm + (qm >= p ? 1 : 0);
        float4 v4 = __ldg((const float4*)g_V + ((size_t)q * NN + mb) * 32 + lane);
        acc.x += wb * v4.x; acc.y += wb * v4.y;
        acc.z += wb * v4.z; acc.w += wb * v4.w;
    }
    ((float4*)out)[((size_t)p * NN + n) * 32 + lane] = acc;
}

// ---------------- launch ----------------
extern "C" void kernel_launch(void* const* d_in, const int* in_sizes, int n_in,
                              void* d_out, int out_size)
{
    const float* aligned = (const float*)d_in[0];
    const float* C       = (const float*)d_in[1];
    const float* WQ      = (const float*)d_in[2];
    const float* WK      = (const float*)d_in[3];
    const float* WV      = (const float*)d_in[4];
    float* out = (float*)d_out;

    void* meanp = nullptr;
    cudaGetSymbolAddress(&meanp, g_meanV4);
    cudaFuncSetAttribute(proj_topk_kernel,
                         cudaFuncAttributeMaxDynamicSharedMemorySize,
                         (int)DSMEM_BYTES);

    cudaMemsetAsync(meanp, 0, VV * DD * sizeof(float));
    proj_topk_kernel<<<TOTAL_BLOCKS, 128, DSMEM_BYTES>>>(aligned, WQ, WK, WV, C);
    gather_kernel<<<NN * VV / 8, 256>>>(out);
}

// round 10
// speedup vs baseline: 1.0740x; 1.0740x over previous
#include <cuda_runtime.h>
#include <math.h>

#define VV 4
#define NN 2048
#define DD 128
#define KK 10
#define NPAIR 12
#define TAU0 0.99f         // static threshold; exact fallback covers any input
#define PROJ_BLOCKS 768
#define TOPK_BLOCKS 1536   // 16 rows per block (4 warps x 4 rows)
#define TOTAL_BLOCKS (PROJ_BLOCKS + TOPK_BLOCKS)  // 2304, bid%3==0 -> proj

// ---------------- scratch (no allocs allowed) ----------------
__device__ float g_Q[VV * NN * DD];
__device__ float g_K[VV * NN * DD];
__device__ float g_V[VV * NN * DD];
__device__ int   g_idx[NPAIR * NN * KK];
__device__ float4 g_meanV4[VV * (DD / 4)];

// total-order 64-bit key: higher value wins; ties -> lower index (matches
// lax.top_k). C >= 0 so monotonic float map is bits | signbit.
__device__ __forceinline__ unsigned long long tk_key(float x, int m)
{
    unsigned int mb = __float_as_uint(x) | 0x80000000u;
    return ((unsigned long long)mb << 32) | (unsigned int)(NN - 1 - m);
}

__device__ __forceinline__ unsigned long long wmax64(unsigned long long k)
{
#pragma unroll
    for (int off = 16; off > 0; off >>= 1) {
        unsigned long long o = __shfl_xor_sync(0xffffffffu, k, off);
        if (o > k) k = o;
    }
    return k;
}

struct ProjS {
    float Xs[32][16];
    float Ws[16][132];
};
struct TopkS {
    float4 buf[4][2][512];               // 4 warps x 2 x 8 KB = 64 KB
    unsigned long long cbuf[4][32];      // 1 KB
};
#define DSMEM_BYTES (sizeof(TopkS))

// exact fallback (rare: ~1% of rows): 10 bounded-rescan extraction rounds
// over the smem-resident row. Emits the exact jax top-k SET (order unused).
__device__ void topk_fallback(const float4* rp4, int lane, int* outp)
{
    unsigned long long bound = ~0ull;
    for (int r = 0; r < KK; ++r) {
        unsigned long long cand = 0ull;
        for (int i = 0; i < 16; ++i) {
            float4 v = rp4[lane + (i << 5)];
            int mb = (lane + (i << 5)) << 2;
            unsigned long long k;
            k = tk_key(v.x, mb + 0); if (k < bound && k > cand) cand = k;
            k = tk_key(v.y, mb + 1); if (k < bound && k > cand) cand = k;
            k = tk_key(v.z, mb + 2); if (k < bound && k > cand) cand = k;
            k = tk_key(v.w, mb + 3); if (k < bound && k > cand) cand = k;
        }
        unsigned long long m = wmax64(cand);
        if (lane == 0) outp[r] = NN - 1 - (int)(m & 0xffffffffu);
        bound = m;
    }
}

// process one smem-resident row: element-ballot capture -> rank-based select.
// No long shfl dependency chains anywhere on the common path.
__device__ __forceinline__ void topk_process_row(
    const float4* rb, unsigned long long* cbuf, int lane, int rowg)
{
    unsigned int lmask = (1u << lane) - 1u;
    int cnt = 0;
#pragma unroll
    for (int i = 0; i < 16; ++i) {
        float4 a = rb[lane + (i << 5)];
        int mb = (lane + (i << 5)) << 2;
        float e[4] = {a.x, a.y, a.z, a.w};
#pragma unroll
        for (int c = 0; c < 4; ++c) {
            bool hit = (e[c] >= TAU0);
            unsigned int bal = __ballot_sync(0xffffffffu, hit);
            if (hit) {
                int pos = cnt + __popc(bal & lmask);
                if (pos < 32) cbuf[pos] = tk_key(e[c], mb + c);
            }
            cnt += __popc(bal);
        }
    }
    __syncwarp();

    int* outp = g_idx + (size_t)rowg * KK;
    if (cnt >= KK && cnt <= 32) {
        unsigned long long mykey = (lane < cnt) ? cbuf[lane] : 0ull;
        int rank = 0;
#pragma unroll
        for (int j = 0; j < 32; ++j) {
            unsigned long long kj = __shfl_sync(0xffffffffu, mykey, j);
            rank += (kj > mykey);
        }
        bool in10 = (lane < cnt) && (rank < KK);   // keys unique -> exactly 10
        unsigned int m10 = __ballot_sync(0xffffffffu, in10);
        if (in10) {
            int pos = __popc(m10 & lmask);
            outp[pos] = NN - 1 - (int)(mykey & 0xffffffffu);
        }
    } else {
        topk_fallback(rb, lane, outp);
    }
}

// ================= fused proj (+meanV) + topk =================
__global__ __launch_bounds__(128) void proj_topk_kernel(
    const float* __restrict__ aligned,
    const float* __restrict__ WQ,
    const float* __restrict__ WK,
    const float* __restrict__ WV,
    const float* __restrict__ C)
{
    extern __shared__ __align__(16) unsigned char smem_raw[];
    int bid = blockIdx.x;
    int tid = threadIdx.x;
    int warp = tid >> 5, lane = tid & 31;

    if (bid % 3 == 0) {
        // ---------------- projection GEMM: 32 rows x 128 cols ----------------
        ProjS& S = *reinterpret_cast<ProjS*>(smem_raw);
        int pb = bid / 3;                 // 0..767
        int tile = pb & 63;
        int vm   = pb >> 6;               // 0..11
        int v = vm / 3, mat = vm % 3;
        const float* W = (mat == 0 ? WQ : (mat == 1 ? WK : WV)) + (size_t)v * DD * DD;
        float* Out = (mat == 0 ? g_Q : (mat == 1 ? g_K : g_V))
                     + (size_t)v * NN * DD + (size_t)tile * 32 * DD;
        const float* X = aligned + (size_t)v * NN * DD + (size_t)tile * 32 * DD;

        float acc[8][4];
#pragma unroll
        for (int i = 0; i < 8; ++i)
#pragma unroll
            for (int c = 0; c < 4; ++c) acc[i][c] = 0.f;

        for (int d0 = 0; d0 < DD; d0 += 16) {
            {
                int r = tid >> 2, f = tid & 3;
                float4 xv = *(const float4*)(X + (size_t)r * DD + d0 + f * 4);
                *(float4*)&S.Xs[r][f * 4] = xv;
            }
#pragma unroll
            for (int j = 0; j < 4; ++j) {
                int lin = tid * 4 + j;
                int e = lin >> 2, f = lin & 3;
                float4 wv = *(const float4*)(W + (size_t)e * DD + d0 + f * 4);
                S.Ws[f * 4 + 0][e] = wv.x;
                S.Ws[f * 4 + 1][e] = wv.y;
                S.Ws[f * 4 + 2][e] = wv.z;
                S.Ws[f * 4 + 3][e] = wv.w;
            }
            __syncthreads();
#pragma unroll
            for (int dd = 0; dd < 16; ++dd) {
                float4 b = *(const float4*)&S.Ws[dd][lane * 4];
#pragma unroll
                for (int i = 0; i < 8; ++i) {
                    float a = S.Xs[warp * 8 + i][dd];
                    acc[i][0] += a * b.x;
                    acc[i][1] += a * b.y;
                    acc[i][2] += a * b.z;
                    acc[i][3] += a * b.w;
                }
            }
            __syncthreads();
        }
#pragma unroll
        for (int i = 0; i < 8; ++i) {
            float4 o = make_float4(acc[i][0], acc[i][1], acc[i][2], acc[i][3]);
            *(float4*)(Out + (size_t)(warp * 8 + i) * DD + lane * 4) = o;
        }
        if (mat == 2) {
#pragma unroll
            for (int c = 0; c < 4; ++c) {
                float s = 0.f;
#pragma unroll
                for (int i = 0; i < 8; ++i) s += acc[i][c];
                atomicAdd((float*)&g_meanV4[0] + v * DD + lane * 4 + c, s);
            }
        }
        return;
    }

    // ------- topk: warp owns 4 rows, double-buffered cp.async, no block syncs -------
    TopkS& S = *reinterpret_cast<TopkS*>(smem_raw);
    int tb = bid - bid / 3 - 1;           // 0..1535
    int rowbase = tb * 16 + warp * 4;     // 4 rows, same (p,q) pair (16 | NN)
    int pair = rowbase / NN, n0 = rowbase % NN;
    int p = pair / 3, qm = pair % 3;
    int q = qm + (qm >= p ? 1 : 0);
    const float* Crow = C + (((size_t)p * VV + q) * NN + n0) * (size_t)NN;

    auto issue_row = [&](int r, int slot) {
        const float4* src = (const float4*)(Crow + (size_t)r * NN);
#pragma unroll
        for (int i = 0; i < 16; ++i) {
            int c = lane + (i << 5);
            unsigned int sa = (unsigned int)__cvta_generic_to_shared(&S.buf[warp][slot][c]);
            asm volatile("cp.async.cg.shared.global [%0], [%1], 16;"
                         :: "r"(sa), "l"(src + c));
        }
        asm volatile("cp.async.commit_group;");
    };

    issue_row(0, 0);
    issue_row(1, 1);

#pragma unroll
    for (int r = 0; r < 4; ++r) {
        if (r < 3) asm volatile("cp.async.wait_group 1;" ::: "memory");
        else       asm volatile("cp.async.wait_group 0;" ::: "memory");
        __syncwarp();
        topk_process_row(&S.buf[warp][r & 1][0], &S.cbuf[warp][0],
                         lane, rowbase + r);
        __syncwarp();                      // select done before buffer reuse
        if (r + 2 < 4) issue_row(r + 2, r & 1);
    }
}

// ---------------- gather: one warp per (p,n), barrier-free ----------------
__global__ __launch_bounds__(256) void gather_kernel(float* __restrict__ out)
{
    __shared__ float sc[8][32];
    __shared__ float smax[8][4];
    __shared__ float ssum[8][4];

    int tid = threadIdx.x;
    int w = tid >> 5, lane = tid & 31;
    int gw = blockIdx.x * 8 + w;          // 0..8191
    int p = gw >> 11, n = gw & (NN - 1);

    int sub = lane & 7, grp = lane >> 3;
    const float4* Qrow = (const float4*)g_Q + ((size_t)p * NN + n) * 32;
    float4 q4[4];
#pragma unroll
    for (int j = 0; j < 4; ++j) q4[j] = Qrow[sub + 8 * j];

    int myidx = 0;
    if (lane < 3 * KK) {
        int pr = p * 3 + lane / KK;
        myidx = g_idx[((size_t)pr * NN + n) * KK + (lane % KK)];
    }

#pragma unroll
    for (int it = 0; it < 8; ++it) {
        int t = it * 4 + grp;
        int tq = (t < 30) ? t : 29;
        int qm = tq / KK;
        int q = qm + (qm >= p ? 1 : 0);
        int m = __shfl_sync(0xffffffffu, myidx, t & 31);
        const float4* Kr = (const float4*)g_K + ((size_t)q * NN + m) * 32;
        float s = 0.f;
#pragma unroll
        for (int j = 0; j < 4; ++j) {
            float4 k4 = __ldg(Kr + sub + 8 * j);
            s += q4[j].x * k4.x + q4[j].y * k4.y + q4[j].z * k4.z + q4[j].w * k4.w;
        }
        s += __shfl_xor_sync(0xffffffffu, s, 1);
        s += __shfl_xor_sync(0xffffffffu, s, 2);
        s += __shfl_xor_sync(0xffffffffu, s, 4);
        if (sub == 0 && t < 30) sc[w][t] = s * 0.08838834764831845f;
    }
    __syncwarp();

    if (lane < 3) {
        float mx = -3.4e38f;
#pragma unroll
        for (int k = 0; k < KK; ++k) mx = fmaxf(mx, sc[w][lane * KK + k]);
        smax[w][lane] = mx;
    }
    __syncwarp();
    if (lane < 3 * KK) sc[w][lane] = expf(sc[w][lane] - smax[w][lane / KK]);
    __syncwarp();
    if (lane < 3) {
        float su = 0.f;
#pragma unroll
        for (int k = 0; k < KK; ++k) su += sc[w][lane * KK + k];
        ssum[w][lane] = su;
    }
    __syncwarp();
    float wt = (lane < 3 * KK) ? sc[w][lane] / ssum[w][lane / KK] : 0.f;

    float4 mv = g_meanV4[p * 32 + lane];
    const float inv = 1.0f / NN;
    float4 acc = make_float4(mv.x * inv, mv.y * inv, mv.z * inv, mv.w * inv);
#pragma unroll
    for (int t = 0; t < 3 * KK; ++t) {
        float wb = __shfl_sync(0xffffffffu, wt, t);
        int   mb = __shfl_sync(0xffffffffu, myidx, t);
        int qm = t / KK;
        int q = qm + (qm >= p ? 1 : 0);
        float4 v4 = __ldg((const float4*)g_V + ((size_t)q * NN + mb) * 32 + lane);
        acc.x += wb * v4.x; acc.y += wb * v4.y;
        acc.z += wb * v4.z; acc.w += wb * v4.w;
    }
    ((float4*)out)[((size_t)p * NN + n) * 32 + lane] = acc;
}

// ---------------- launch ----------------
extern "C" void kernel_launch(void* const* d_in, const int* in_sizes, int n_in,
                              void* d_out, int out_size)
{
    const float* aligned = (const float*)d_in[0];
    const float* C       = (const float*)d_in[1];
    const float* WQ      = (const float*)d_in[2];
    const float* WK      = (const float*)d_in[3];
    const float* WV      = (const float*)d_in[4];
    float* out = (float*)d_out;

    void* meanp = nullptr;
    cudaGetSymbolAddress(&meanp, g_meanV4);
    cudaFuncSetAttribute(proj_topk_kernel,
                         cudaFuncAttributeMaxDynamicSharedMemorySize,
                         (int)DSMEM_BYTES);

    cudaMemsetAsync(meanp, 0, VV * DD * sizeof(float));
    proj_topk_kernel<<<TOTAL_BLOCKS, 128, DSMEM_BYTES>>>(aligned, WQ, WK, WV, C);
    gather_kernel<<<NN * VV / 8, 256>>>(out);
}

// round 11
// speedup vs baseline: 1.4890x; 1.3864x over previous
#include <cuda_runtime.h>
#include <math.h>

#define VV 4
#define NN 2048
#define DD 128
#define KK 10
#define NPAIR 12
#define TAU0 0.99f         // static threshold; exact fallback covers any input
#define PROJ_BLOCKS 768    // 12 mats x 64 tiles (32 rows)
#define TOPK_BLOCKS 6144   // 24576 rows / 4 per block
#define TOTAL_BLOCKS (PROJ_BLOCKS + TOPK_BLOCKS)   // 6912, 1:8 interleave

// ---------------- scratch (no allocs allowed) ----------------
__device__ float g_Q[VV * NN * DD];
__device__ float g_K[VV * NN * DD];
__device__ float g_V[VV * NN * DD];
__device__ int   g_idx[NPAIR * NN * KK];
__device__ float4 g_meanV4[VV * (DD / 4)];

// total-order 64-bit key: higher value wins; ties -> lower index (matches
// lax.top_k). C >= 0 so monotonic float map is bits | signbit.
__device__ __forceinline__ unsigned long long tk_key(float x, int m)
{
    unsigned int mb = __float_as_uint(x) | 0x80000000u;
    return ((unsigned long long)mb << 32) | (unsigned int)(NN - 1 - m);
}

__device__ __forceinline__ unsigned long long wmax64(unsigned long long k)
{
#pragma unroll
    for (int off = 16; off > 0; off >>= 1) {
        unsigned long long o = __shfl_xor_sync(0xffffffffu, k, off);
        if (o > k) k = o;
    }
    return k;
}

struct ProjS {
    float Xs[32][16];
    float Ws[16][132];
};
struct TopkS {
    float4 rb[4][512];                   // 4 warps x 8 KB = 32 KB
    unsigned long long cbuf[4][32];      // 1 KB
};

// exact fallback (rare: ~1% of rows): 10 bounded-rescan extraction rounds
// over the smem-resident row. Emits the exact jax top-k SET.
__device__ void topk_fallback(const float4* rp4, int lane, int* outp)
{
    unsigned long long bound = ~0ull;
    for (int r = 0; r < KK; ++r) {
        unsigned long long cand = 0ull;
        for (int i = 0; i < 16; ++i) {
            float4 v = rp4[lane + (i << 5)];
            int mb = (lane + (i << 5)) << 2;
            unsigned long long k;
            k = tk_key(v.x, mb + 0); if (k < bound && k > cand) cand = k;
            k = tk_key(v.y, mb + 1); if (k < bound && k > cand) cand = k;
            k = tk_key(v.z, mb + 2); if (k < bound && k > cand) cand = k;
            k = tk_key(v.w, mb + 3); if (k < bound && k > cand) cand = k;
        }
        unsigned long long m = wmax64(cand);
        if (lane == 0) outp[r] = NN - 1 - (int)(m & 0xffffffffu);
        bound = m;
    }
}

// process one smem-resident row: element-ballot capture (<=32 candidates)
// -> rank-based select (32 independent broadcast compares, no chains).
__device__ __forceinline__ void topk_process_row(
    const float4* rb, unsigned long long* cbuf, int lane, int rowg)
{
    unsigned int lmask = (1u << lane) - 1u;
    int cnt = 0;
#pragma unroll
    for (int i = 0; i < 16; ++i) {
        float4 a = rb[lane + (i << 5)];
        int mb = (lane + (i << 5)) << 2;
        float e[4] = {a.x, a.y, a.z, a.w};
#pragma unroll
        for (int c = 0; c < 4; ++c) {
            bool hit = (e[c] >= TAU0);
            unsigned int bal = __ballot_sync(0xffffffffu, hit);
            if (hit) {
                int pos = cnt + __popc(bal & lmask);
                if (pos < 32) cbuf[pos] = tk_key(e[c], mb + c);
            }
            cnt += __popc(bal);
        }
    }
    __syncwarp();

    int* outp = g_idx + (size_t)rowg * KK;
    if (cnt >= KK && cnt <= 32) {
        unsigned long long mykey = (lane < cnt) ? cbuf[lane] : 0ull;
        int rank = 0;
#pragma unroll
        for (int j = 0; j < 32; ++j) {
            unsigned long long kj = __shfl_sync(0xffffffffu, mykey, j);
            rank += (kj > mykey);
        }
        bool in10 = (lane < cnt) && (rank < KK);   // keys unique -> exactly 10
        unsigned int m10 = __ballot_sync(0xffffffffu, in10);
        if (in10) {
            int pos = __popc(m10 & lmask);
            outp[pos] = NN - 1 - (int)(mykey & 0xffffffffu);
        }
    } else {
        topk_fallback(rb, lane, outp);
    }
}

// ================= fused proj (+meanV) + topk =================
__global__ __launch_bounds__(128, 6) void proj_topk_kernel(
    const float* __restrict__ aligned,
    const float* __restrict__ WQ,
    const float* __restrict__ WK,
    const float* __restrict__ WV,
    const float* __restrict__ C)
{
    __shared__ __align__(16) unsigned char smem_raw[sizeof(TopkS)];
    int bid = blockIdx.x;
    int tid = threadIdx.x;
    int warp = tid >> 5, lane = tid & 31;

    if (bid % 9 == 0) {
        // ---------------- projection GEMM: 32 rows x 128 cols ----------------
        ProjS& S = *reinterpret_cast<ProjS*>(smem_raw);
        int pb = bid / 9;                 // 0..767
        int tile = pb & 63;
        int vm   = pb >> 6;               // 0..11
        int v = vm / 3, mat = vm % 3;
        const float* W = (mat == 0 ? WQ : (mat == 1 ? WK : WV)) + (size_t)v * DD * DD;
        float* Out = (mat == 0 ? g_Q : (mat == 1 ? g_K : g_V))
                     + (size_t)v * NN * DD + (size_t)tile * 32 * DD;
        const float* X = aligned + (size_t)v * NN * DD + (size_t)tile * 32 * DD;

        float acc[8][4];
#pragma unroll
        for (int i = 0; i < 8; ++i)
#pragma unroll
            for (int c = 0; c < 4; ++c) acc[i][c] = 0.f;

        for (int d0 = 0; d0 < DD; d0 += 16) {
            {
                int r = tid >> 2, f = tid & 3;
                float4 xv = *(const float4*)(X + (size_t)r * DD + d0 + f * 4);
                *(float4*)&S.Xs[r][f * 4] = xv;
            }
#pragma unroll
            for (int j = 0; j < 4; ++j) {
                int lin = tid * 4 + j;
                int e = lin >> 2, f = lin & 3;
                float4 wv = *(const float4*)(W + (size_t)e * DD + d0 + f * 4);
                S.Ws[f * 4 + 0][e] = wv.x;
                S.Ws[f * 4 + 1][e] = wv.y;
                S.Ws[f * 4 + 2][e] = wv.z;
                S.Ws[f * 4 + 3][e] = wv.w;
            }
            __syncthreads();
#pragma unroll
            for (int dd = 0; dd < 16; ++dd) {
                float4 b = *(const float4*)&S.Ws[dd][lane * 4];
#pragma unroll
                for (int i = 0; i < 8; ++i) {
                    float a = S.Xs[warp * 8 + i][dd];
                    acc[i][0] += a * b.x;
                    acc[i][1] += a * b.y;
                    acc[i][2] += a * b.z;
                    acc[i][3] += a * b.w;
                }
            }
            __syncthreads();
        }
#pragma unroll
        for (int i = 0; i < 8; ++i) {
            float4 o = make_float4(acc[i][0], acc[i][1], acc[i][2], acc[i][3]);
            *(float4*)(Out + (size_t)(warp * 8 + i) * DD + lane * 4) = o;
        }
        if (mat == 2) {
            // fused meanV: per-thread column partials over this tile's 8 rows
#pragma unroll
            for (int c = 0; c < 4; ++c) {
                float s = 0.f;
#pragma unroll
                for (int i = 0; i < 8; ++i) s += acc[i][c];
                atomicAdd((float*)&g_meanV4[0] + v * DD + lane * 4 + c, s);
            }
        }
        return;
    }

    // ---------------- topk: 4 warps x 1 row, cp.async-staged ----------------
    TopkS& S = *reinterpret_cast<TopkS*>(smem_raw);
    int tb = bid - bid / 9 - 1;           // 0..6143
    int rowg = tb * 4 + warp;             // 0..24575
    int pair = rowg / NN, n = rowg % NN;
    int p = pair / 3, qm = pair % 3;
    int q = qm + (qm >= p ? 1 : 0);
    const float4* rowp4 = (const float4*)
        (C + (((size_t)p * VV + q) * NN + n) * (size_t)NN);

    // stage the whole 8KB row via cp.async (deep MLP, zero reg pressure)
#pragma unroll
    for (int i = 0; i < 16; ++i) {
        int c = lane + (i << 5);
        unsigned int sa = (unsigned int)__cvta_generic_to_shared(&S.rb[warp][c]);
        asm volatile("cp.async.cg.shared.global [%0], [%1], 16;"
                     :: "r"(sa), "l"(rowp4 + c));
    }
    asm volatile("cp.async.commit_group;");
    asm volatile("cp.async.wait_group 0;" ::: "memory");
    __syncwarp();

    topk_process_row(&S.rb[warp][0], &S.cbuf[warp][0], lane, rowg);
}

// ---------------- gather: one warp per (p,n), barrier-free ----------------
__global__ __launch_bounds__(256) void gather_kernel(float* __restrict__ out)
{
    __shared__ float sc[8][32];
    __shared__ float smax[8][4];
    __shared__ float ssum[8][4];

    int tid = threadIdx.x;
    int w = tid >> 5, lane = tid & 31;
    int gw = blockIdx.x * 8 + w;          // 0..8191
    int p = gw >> 11, n = gw & (NN - 1);

    int sub = lane & 7, grp = lane >> 3;
    const float4* Qrow = (const float4*)g_Q + ((size_t)p * NN + n) * 32;
    float4 q4[4];
#pragma unroll
    for (int j = 0; j < 4; ++j) q4[j] = Qrow[sub + 8 * j];

    int myidx = 0;
    if (lane < 3 * KK) {
        int pr = p * 3 + lane / KK;
        myidx = g_idx[((size_t)pr * NN + n) * KK + (lane % KK)];
    }

#pragma unroll
    for (int it = 0; it < 8; ++it) {
        int t = it * 4 + grp;
        int tq = (t < 30) ? t : 29;
        int qm = tq / KK;
        int q = qm + (qm >= p ? 1 : 0);
        int m = __shfl_sync(0xffffffffu, myidx, t & 31);
        const float4* Kr = (const float4*)g_K + ((size_t)q * NN + m) * 32;
        float s = 0.f;
#pragma unroll
        for (int j = 0; j < 4; ++j) {
            float4 k4 = __ldg(Kr + sub + 8 * j);
            s += q4[j].x * k4.x + q4[j].y * k4.y + q4[j].z * k4.z + q4[j].w * k4.w;
        }
        s += __shfl_xor_sync(0xffffffffu, s, 1);
        s += __shfl_xor_sync(0xffffffffu, s, 2);
        s += __shfl_xor_sync(0xffffffffu, s, 4);
        if (sub == 0 && t < 30) sc[w][t] = s * 0.08838834764831845f;
    }
    __syncwarp();

    if (lane < 3) {
        float mx = -3.4e38f;
#pragma unroll
        for (int k = 0; k < KK; ++k) mx = fmaxf(mx, sc[w][lane * KK + k]);
        smax[w][lane] = mx;
    }
    __syncwarp();
    if (lane < 3 * KK) sc[w][lane] = expf(sc[w][lane] - smax[w][lane / KK]);
    __syncwarp();
    if (lane < 3) {
        float su = 0.f;
#pragma unroll
        for (int k = 0; k < KK; ++k) su += sc[w][lane * KK + k];
        ssum[w][lane] = su;
    }
    __syncwarp();
    float wt = (lane < 3 * KK) ? sc[w][lane] / ssum[w][lane / KK] : 0.f;

    float4 mv = g_meanV4[p * 32 + lane];
    const float inv = 1.0f / NN;
    float4 acc = make_float4(mv.x * inv, mv.y * inv, mv.z * inv, mv.w * inv);
#pragma unroll
    for (int t = 0; t < 3 * KK; ++t) {
        float wb = __shfl_sync(0xffffffffu, wt, t);
        int   mb = __shfl_sync(0xffffffffu, myidx, t);
        int qm = t / KK;
        int q = qm + (qm >= p ? 1 : 0);
        float4 v4 = __ldg((const float4*)g_V + ((size_t)q * NN + mb) * 32 + lane);
        acc.x += wb * v4.x; acc.y += wb * v4.y;
        acc.z += wb * v4.z; acc.w += wb * v4.w;
    }
    ((float4*)out)[((size_t)p * NN + n) * 32 + lane] = acc;
}

// ---------------- launch ----------------
extern "C" void kernel_launch(void* const* d_in, const int* in_sizes, int n_in,
                              void* d_out, int out_size)
{
    const float* aligned = (const float*)d_in[0];
    const float* C       = (const float*)d_in[1];
    const float* WQ      = (const float*)d_in[2];
    const float* WK      = (const float*)d_in[3];
    const float* WV      = (const float*)d_in[4];
    float* out = (float*)d_out;

    void* meanp = nullptr;
    cudaGetSymbolAddress(&meanp, g_meanV4);

    cudaMemsetAsync(meanp, 0, VV * DD * sizeof(float));
    proj_topk_kernel<<<TOTAL_BLOCKS, 128>>>(aligned, WQ, WK, WV, C);
    gather_kernel<<<NN * VV / 8, 256>>>(out);
}

// round 12
// speedup vs baseline: 1.5257x; 1.0246x over previous
#include <cuda_runtime.h>
#include <math.h>

#define VV 4
#define NN 2048
#define DD 128
#define KK 10
#define NPAIR 12
#define TAU0 0.99f         // static threshold; exact fallback covers any input
#define PROJ_BLOCKS 384    // 12 mats x 32 tiles (64 rows)
#define TOPK_BLOCKS 1536   // 16 rows per block (8 warps x 2 rows)
#define TOTAL_BLOCKS (PROJ_BLOCKS + TOPK_BLOCKS)   // 1920, bid%5==0 -> proj

// ---------------- scratch (no allocs allowed) ----------------
__device__ float g_Q[VV * NN * DD];
__device__ float g_K[VV * NN * DD];
__device__ float g_V[VV * NN * DD];
__device__ int   g_idx[NPAIR * NN * KK];
__device__ float4 g_meanV4[VV * (DD / 4)];

// total-order 64-bit key: higher value wins; ties -> lower index (matches
// lax.top_k). C >= 0 so monotonic float map is bits | signbit.
__device__ __forceinline__ unsigned long long tk_key(float x, int m)
{
    unsigned int mb = __float_as_uint(x) | 0x80000000u;
    return ((unsigned long long)mb << 32) | (unsigned int)(NN - 1 - m);
}

__device__ __forceinline__ unsigned long long wmax64(unsigned long long k)
{
#pragma unroll
    for (int off = 16; off > 0; off >>= 1) {
        unsigned long long o = __shfl_xor_sync(0xffffffffu, k, off);
        if (o > k) k = o;
    }
    return k;
}

struct ProjS {
    float Xs[64][16];
    float Ws[16][132];
};
struct TopkS {
    unsigned long long cbuf[8][2][32];   // 4 KB
};

// exact fallback (rare: ~1% of rows): 10 bounded-rescan extraction rounds
// over the (L2-resident) global row. Emits the exact jax top-k SET.
__device__ void topk_fallback(const float4* __restrict__ rp4, int lane, int* outp)
{
    unsigned long long bound = ~0ull;
    for (int r = 0; r < KK; ++r) {
        unsigned long long cand = 0ull;
        for (int i = 0; i < 16; ++i) {
            float4 v = __ldg(rp4 + lane + (i << 5));
            int mb = (lane + (i << 5)) << 2;
            unsigned long long k;
            k = tk_key(v.x, mb + 0); if (k < bound && k > cand) cand = k;
            k = tk_key(v.y, mb + 1); if (k < bound && k > cand) cand = k;
            k = tk_key(v.z, mb + 2); if (k < bound && k > cand) cand = k;
            k = tk_key(v.w, mb + 3); if (k < bound && k > cand) cand = k;
        }
        unsigned long long m = wmax64(cand);
        if (lane == 0) outp[r] = NN - 1 - (int)(m & 0xffffffffu);
        bound = m;
    }
}

// capture 4 elements of one row via per-element ballots
__device__ __forceinline__ void capture4(
    float4 a, int mb, float tau, unsigned int lmask,
    unsigned long long* cbuf, int& cnt)
{
    float e[4] = {a.x, a.y, a.z, a.w};
#pragma unroll
    for (int c = 0; c < 4; ++c) {
        bool hit = (e[c] >= tau);
        unsigned int bal = __ballot_sync(0xffffffffu, hit);
        if (hit) {
            int pos = cnt + __popc(bal & lmask);
            if (pos < 32) cbuf[pos] = tk_key(e[c], mb + c);
        }
        cnt += __popc(bal);
    }
}

// rank-based select over <=32 candidates (no shfl dependency chains)
__device__ __forceinline__ void select10(
    const unsigned long long* cbuf, int cnt, int lane,
    unsigned int lmask, const float4* grow, int* outp)
{
    if (cnt >= KK && cnt <= 32) {
        unsigned long long mykey = (lane < cnt) ? cbuf[lane] : 0ull;
        int rank = 0;
#pragma unroll
        for (int j = 0; j < 32; ++j) {
            unsigned long long kj = __shfl_sync(0xffffffffu, mykey, j);
            rank += (kj > mykey);
        }
        bool in10 = (lane < cnt) && (rank < KK);   // keys unique -> exactly 10
        unsigned int m10 = __ballot_sync(0xffffffffu, in10);
        if (in10) {
            int pos = __popc(m10 & lmask);
            outp[pos] = NN - 1 - (int)(mykey & 0xffffffffu);
        }
    } else {
        topk_fallback(grow, lane, outp);
    }
}

// ================= fused proj (+meanV) + topk =================
__global__ __launch_bounds__(256, 4) void proj_topk_kernel(
    const float* __restrict__ aligned,
    const float* __restrict__ WQ,
    const float* __restrict__ WK,
    const float* __restrict__ WV,
    const float* __restrict__ C)
{
    __shared__ __align__(16) unsigned char smem_raw[sizeof(ProjS) > sizeof(TopkS)
                                                    ? sizeof(ProjS) : sizeof(TopkS)];
    int bid = blockIdx.x;
    int tid = threadIdx.x;
    int warp = tid >> 5, lane = tid & 31;

    if (bid % 5 == 0) {
        // ---------------- projection GEMM: 64 rows x 128 cols ----------------
        ProjS& S = *reinterpret_cast<ProjS*>(smem_raw);
        int pb = bid / 5;                 // 0..383
        int tile = pb & 31;
        int vm   = pb >> 5;               // 0..11
        int v = vm / 3, mat = vm % 3;
        const float* W = (mat == 0 ? WQ : (mat == 1 ? WK : WV)) + (size_t)v * DD * DD;
        float* Out = (mat == 0 ? g_Q : (mat == 1 ? g_K : g_V))
                     + (size_t)v * NN * DD + (size_t)tile * 64 * DD;
        const float* X = aligned + (size_t)v * NN * DD + (size_t)tile * 64 * DD;

        float acc[8][4];
#pragma unroll
        for (int i = 0; i < 8; ++i)
#pragma unroll
            for (int c = 0; c < 4; ++c) acc[i][c] = 0.f;

        for (int d0 = 0; d0 < DD; d0 += 16) {
            {
                int r = tid >> 2, f = tid & 3;
                float4 xv = *(const float4*)(X + (size_t)r * DD + d0 + f * 4);
                *(float4*)&S.Xs[r][f * 4] = xv;
            }
#pragma unroll
            for (int j = 0; j < 2; ++j) {
                int lin = tid * 2 + j;
                int e = lin >> 2, f = lin & 3;
                float4 wv = *(const float4*)(W + (size_t)e * DD + d0 + f * 4);
                S.Ws[f * 4 + 0][e] = wv.x;
                S.Ws[f * 4 + 1][e] = wv.y;
                S.Ws[f * 4 + 2][e] = wv.z;
                S.Ws[f * 4 + 3][e] = wv.w;
            }
            __syncthreads();
#pragma unroll
            for (int dd = 0; dd < 16; ++dd) {
                float4 b = *(const float4*)&S.Ws[dd][lane * 4];
#pragma unroll
                for (int i = 0; i < 8; ++i) {
                    float a = S.Xs[warp * 8 + i][dd];
                    acc[i][0] += a * b.x;
                    acc[i][1] += a * b.y;
                    acc[i][2] += a * b.z;
                    acc[i][3] += a * b.w;
                }
            }
            __syncthreads();
        }
#pragma unroll
        for (int i = 0; i < 8; ++i) {
            float4 o = make_float4(acc[i][0], acc[i][1], acc[i][2], acc[i][3]);
            *(float4*)(Out + (size_t)(warp * 8 + i) * DD + lane * 4) = o;
        }
        if (mat == 2) {
            // fused meanV: per-thread column partials over this tile's 8 rows
#pragma unroll
            for (int c = 0; c < 4; ++c) {
                float s = 0.f;
#pragma unroll
                for (int i = 0; i < 8; ++i) s += acc[i][c];
                atomicAdd((float*)&g_meanV4[0] + v * DD + lane * 4 + c, s);
            }
        }
        return;
    }

    // ------- topk: 8 warps x 2 interleaved rows, direct streaming LDG -------
    TopkS& S = *reinterpret_cast<TopkS*>(smem_raw);
    int tb = bid - bid / 5 - 1;           // 0..1535
    int rowbase = tb * 16 + warp * 2;     // rows rowbase, rowbase+1 (same pair)
    int pair = rowbase / NN, n0 = rowbase % NN;
    int p = pair / 3, qm = pair % 3;
    int q = qm + (qm >= p ? 1 : 0);
    const float4* rA = (const float4*)
        (C + (((size_t)p * VV + q) * NN + n0) * (size_t)NN);
    const float4* rB = rA + (NN / 4);

    unsigned int lmask = (1u << lane) - 1u;
    unsigned long long* cbA = &S.cbuf[warp][0][0];
    unsigned long long* cbB = &S.cbuf[warp][1][0];
    int cntA = 0, cntB = 0;

#pragma unroll
    for (int i = 0; i < 16; ++i) {
        // both rows' loads issued before any consumption -> sustained MLP
        float4 a = __ldcs(rA + lane + (i << 5));
        float4 b = __ldcs(rB + lane + (i << 5));
        int mb = (lane + (i << 5)) << 2;
        capture4(a, mb, TAU0, lmask, cbA, cntA);
        capture4(b, mb, TAU0, lmask, cbB, cntB);
    }
    __syncwarp();

    select10(cbA, cntA, lane, lmask, rA, g_idx + (size_t)rowbase * KK);
    select10(cbB, cntB, lane, lmask, rB, g_idx + (size_t)(rowbase + 1) * KK);
}

// ---------------- gather: one warp per (p,n), barrier-free ----------------
__global__ __launch_bounds__(256) void gather_kernel(float* __restrict__ out)
{
    __shared__ float sc[8][32];
    __shared__ float smax[8][4];
    __shared__ float ssum[8][4];

    int tid = threadIdx.x;
    int w = tid >> 5, lane = tid & 31;
    int gw = blockIdx.x * 8 + w;          // 0..8191
    int p = gw >> 11, n = gw & (NN - 1);

    int sub = lane & 7, grp = lane >> 3;
    const float4* Qrow = (const float4*)g_Q + ((size_t)p * NN + n) * 32;
    float4 q4[4];
#pragma unroll
    for (int j = 0; j < 4; ++j) q4[j] = Qrow[sub + 8 * j];

    int myidx = 0;
    if (lane < 3 * KK) {
        int pr = p * 3 + lane / KK;
        myidx = g_idx[((size_t)pr * NN + n) * KK + (lane % KK)];
    }

#pragma unroll
    for (int it = 0; it < 8; ++it) {
        int t = it * 4 + grp;
        int tq = (t < 30) ? t : 29;
        int qm = tq / KK;
        int q = qm + (qm >= p ? 1 : 0);
        int m = __shfl_sync(0xffffffffu, myidx, t & 31);
        const float4* Kr = (const float4*)g_K + ((size_t)q * NN + m) * 32;
        float s = 0.f;
#pragma unroll
        for (int j = 0; j < 4; ++j) {
            float4 k4 = __ldg(Kr + sub + 8 * j);
            s += q4[j].x * k4.x + q4[j].y * k4.y + q4[j].z * k4.z + q4[j].w * k4.w;
        }
        s += __shfl_xor_sync(0xffffffffu, s, 1);
        s += __shfl_xor_sync(0xffffffffu, s, 2);
        s += __shfl_xor_sync(0xffffffffu, s, 4);
        if (sub == 0 && t < 30) sc[w][t] = s * 0.08838834764831845f;
    }
    __syncwarp();

    if (lane < 3) {
        float mx = -3.4e38f;
#pragma unroll
        for (int k = 0; k < KK; ++k) mx = fmaxf(mx, sc[w][lane * KK + k]);
        smax[w][lane] = mx;
    }
    __syncwarp();
    if (lane < 3 * KK) sc[w][lane] = expf(sc[w][lane] - smax[w][lane / KK]);
    __syncwarp();
    if (lane < 3) {
        float su = 0.f;
#pragma unroll
        for (int k = 0; k < KK; ++k) su += sc[w][lane * KK + k];
        ssum[w][lane] = su;
    }
    __syncwarp();
    float wt = (lane < 3 * KK) ? sc[w][lane] / ssum[w][lane / KK] : 0.f;

    float4 mv = g_meanV4[p * 32 + lane];
    const float inv = 1.0f / NN;
    float4 acc = make_float4(mv.x * inv, mv.y * inv, mv.z * inv, mv.w * inv);
#pragma unroll
    for (int t = 0; t < 3 * KK; ++t) {
        float wb = __shfl_sync(0xffffffffu, wt, t);
        int   mb = __shfl_sync(0xffffffffu, myidx, t);
        int qm = t / KK;
        int q = qm + (qm >= p ? 1 : 0);
        float4 v4 = __ldg((const float4*)g_V + ((size_t)q * NN + mb) * 32 + lane);
        acc.x += wb * v4.x; acc.y += wb * v4.y;
        acc.z += wb * v4.z; acc.w += wb * v4.w;
    }
    ((float4*)out)[((size_t)p * NN + n) * 32 + lane] = acc;
}

// ---------------- launch ----------------
extern "C" void kernel_launch(void* const* d_in, const int* in_sizes, int n_in,
                              void* d_out, int out_size)
{
    const float* aligned = (const float*)d_in[0];
    const float* C       = (const float*)d_in[1];
    const float* WQ      = (const float*)d_in[2];
    const float* WK      = (const float*)d_in[3];
    const float* WV      = (const float*)d_in[4];
    float* out = (float*)d_out;

    void* meanp = nullptr;
    cudaGetSymbolAddress(&meanp, g_meanV4);

    cudaMemsetAsync(meanp, 0, VV * DD * sizeof(float));
    proj_topk_kernel<<<TOTAL_BLOCKS, 256>>>(aligned, WQ, WK, WV, C);
    gather_kernel<<<NN * VV / 8, 256>>>(out);
}

// round 13
// speedup vs baseline: 1.5305x; 1.0031x over previous
#include <cuda_runtime.h>
#include <math.h>

#define VV 4
#define NN 2048
#define DD 128
#define KK 10
#define NPAIR 12
#define TAU0 0.99f         // static threshold; exact fallback covers any input
#define PROJ_BLOCKS 768    // 12 mats x 64 tiles (32 rows)
#define TOPK_BLOCKS 1536   // 16 rows per block (8 warps x 2 rows)
#define TOTAL_BLOCKS (PROJ_BLOCKS + TOPK_BLOCKS)   // 2304, bid%3==0 -> proj

// ---------------- scratch (no allocs allowed) ----------------
__device__ float g_Q[VV * NN * DD];
__device__ float g_K[VV * NN * DD];
__device__ float g_V[VV * NN * DD];
__device__ int   g_idx[NPAIR * NN * KK];
__device__ float4 g_meanV4[VV * (DD / 4)];

// total-order 64-bit key: higher value wins; ties -> lower index (matches
// lax.top_k). C >= 0 so monotonic float map is bits | signbit.
__device__ __forceinline__ unsigned long long tk_key(float x, int m)
{
    unsigned int mb = __float_as_uint(x) | 0x80000000u;
    return ((unsigned long long)mb << 32) | (unsigned int)(NN - 1 - m);
}

__device__ __forceinline__ unsigned long long wmax64(unsigned long long k)
{
#pragma unroll
    for (int off = 16; off > 0; off >>= 1) {
        unsigned long long o = __shfl_xor_sync(0xffffffffu, k, off);
        if (o > k) k = o;
    }
    return k;
}

struct ProjS {
    float Xs[32][16];
    float Ws[16][132];
};
struct TopkS {
    unsigned long long cbuf[8][2][32];   // 4 KB
};

// exact fallback (rare: ~1.5% of rows): 10 bounded-rescan extraction rounds
// over the (L2-resident) global row. Emits the exact jax top-k SET.
__device__ void topk_fallback(const float4* __restrict__ rp4, int lane, int* outp)
{
    unsigned long long bound = ~0ull;
    for (int r = 0; r < KK; ++r) {
        unsigned long long cand = 0ull;
        for (int i = 0; i < 16; ++i) {
            float4 v = __ldg(rp4 + lane + (i << 5));
            int mb = (lane + (i << 5)) << 2;
            unsigned long long k;
            k = tk_key(v.x, mb + 0); if (k < bound && k > cand) cand = k;
            k = tk_key(v.y, mb + 1); if (k < bound && k > cand) cand = k;
            k = tk_key(v.z, mb + 2); if (k < bound && k > cand) cand = k;
            k = tk_key(v.w, mb + 3); if (k < bound && k > cand) cand = k;
        }
        unsigned long long m = wmax64(cand);
        if (lane == 0) outp[r] = NN - 1 - (int)(m & 0xffffffffu);
        bound = m;
    }
}

// capture 4 elements of one row via per-element ballots
__device__ __forceinline__ void capture4(
    float4 a, int mb, float tau, unsigned int lmask,
    unsigned long long* cbuf, int& cnt)
{
    float e[4] = {a.x, a.y, a.z, a.w};
#pragma unroll
    for (int c = 0; c < 4; ++c) {
        bool hit = (e[c] >= tau);
        unsigned int bal = __ballot_sync(0xffffffffu, hit);
        if (hit) {
            int pos = cnt + __popc(bal & lmask);
            if (pos < 32) cbuf[pos] = tk_key(e[c], mb + c);
        }
        cnt += __popc(bal);
    }
}

// rank-based select over <=32 candidates (no shfl dependency chains)
__device__ __forceinline__ void select10(
    const unsigned long long* cbuf, int cnt, int lane,
    unsigned int lmask, const float4* grow, int* outp)
{
    if (cnt >= KK && cnt <= 32) {
        unsigned long long mykey = (lane < cnt) ? cbuf[lane] : 0ull;
        int rank = 0;
#pragma unroll
        for (int j = 0; j < 32; ++j) {
            unsigned long long kj = __shfl_sync(0xffffffffu, mykey, j);
            rank += (kj > mykey);
        }
        bool in10 = (lane < cnt) && (rank < KK);   // keys unique -> exactly 10
        unsigned int m10 = __ballot_sync(0xffffffffu, in10);
        if (in10) {
            int pos = __popc(m10 & lmask);
            outp[pos] = NN - 1 - (int)(mykey & 0xffffffffu);
        }
    } else {
        topk_fallback(grow, lane, outp);
    }
}

// ================= fused proj (+meanV) + topk =================
__global__ __launch_bounds__(256, 5) void proj_topk_kernel(
    const float* __restrict__ aligned,
    const float* __restrict__ WQ,
    const float* __restrict__ WK,
    const float* __restrict__ WV,
    const float* __restrict__ C)
{
    __shared__ __align__(16) unsigned char smem_raw[sizeof(ProjS) > sizeof(TopkS)
                                                    ? sizeof(ProjS) : sizeof(TopkS)];
    int bid = blockIdx.x;
    int tid = threadIdx.x;
    int warp = tid >> 5, lane = tid & 31;

    if (bid % 3 == 0) {
        // ------------ projection GEMM: 32 rows x 128 cols, 16 acc/thread ------------
        ProjS& S = *reinterpret_cast<ProjS*>(smem_raw);
        int pb = bid / 3;                 // 0..767
        int tile = pb & 63;
        int vm   = pb >> 6;               // 0..11
        int v = vm / 3, mat = vm % 3;
        const float* W = (mat == 0 ? WQ : (mat == 1 ? WK : WV)) + (size_t)v * DD * DD;
        float* Out = (mat == 0 ? g_Q : (mat == 1 ? g_K : g_V))
                     + (size_t)v * NN * DD + (size_t)tile * 32 * DD;
        const float* X = aligned + (size_t)v * NN * DD + (size_t)tile * 32 * DD;

        float acc[4][4];
#pragma unroll
        for (int i = 0; i < 4; ++i)
#pragma unroll
            for (int c = 0; c < 4; ++c) acc[i][c] = 0.f;

        for (int d0 = 0; d0 < DD; d0 += 16) {
            if (tid < 128) {
                int r = tid >> 2, f = tid & 3;
                float4 xv = *(const float4*)(X + (size_t)r * DD + d0 + f * 4);
                *(float4*)&S.Xs[r][f * 4] = xv;
            }
#pragma unroll
            for (int j = 0; j < 2; ++j) {
                int lin = tid * 2 + j;
                int e = lin >> 2, f = lin & 3;
                float4 wv = *(const float4*)(W + (size_t)e * DD + d0 + f * 4);
                S.Ws[f * 4 + 0][e] = wv.x;
                S.Ws[f * 4 + 1][e] = wv.y;
                S.Ws[f * 4 + 2][e] = wv.z;
                S.Ws[f * 4 + 3][e] = wv.w;
            }
            __syncthreads();
#pragma unroll
            for (int dd = 0; dd < 16; ++dd) {
                float4 b = *(const float4*)&S.Ws[dd][lane * 4];
#pragma unroll
                for (int i = 0; i < 4; ++i) {
                    float a = S.Xs[warp * 4 + i][dd];
                    acc[i][0] += a * b.x;
                    acc[i][1] += a * b.y;
                    acc[i][2] += a * b.z;
                    acc[i][3] += a * b.w;
                }
            }
            __syncthreads();
        }
#pragma unroll
        for (int i = 0; i < 4; ++i) {
            float4 o = make_float4(acc[i][0], acc[i][1], acc[i][2], acc[i][3]);
            *(float4*)(Out + (size_t)(warp * 4 + i) * DD + lane * 4) = o;
        }
        if (mat == 2) {
            // fused meanV: per-thread column partials over this tile's 4 rows
#pragma unroll
            for (int c = 0; c < 4; ++c) {
                float s = 0.f;
#pragma unroll
                for (int i = 0; i < 4; ++i) s += acc[i][c];
                atomicAdd((float*)&g_meanV4[0] + v * DD + lane * 4 + c, s);
            }
        }
        return;
    }

    // ------- topk: 8 warps x 2 interleaved rows, direct streaming LDG -------
    TopkS& S = *reinterpret_cast<TopkS*>(smem_raw);
    int tb = bid - bid / 3 - 1;           // 0..1535
    int rowbase = tb * 16 + warp * 2;     // rows rowbase, rowbase+1 (same pair)
    int pair = rowbase / NN, n0 = rowbase % NN;
    int p = pair / 3, qm = pair % 3;
    int q = qm + (qm >= p ? 1 : 0);
    const float4* rA = (const float4*)
        (C + (((size_t)p * VV + q) * NN + n0) * (size_t)NN);
    const float4* rB = rA + (NN / 4);

    unsigned int lmask = (1u << lane) - 1u;
    unsigned long long* cbA = &S.cbuf[warp][0][0];
    unsigned long long* cbB = &S.cbuf[warp][1][0];
    int cntA = 0, cntB = 0;

#pragma unroll
    for (int i = 0; i < 16; ++i) {
        // both rows' loads issued before any consumption -> sustained MLP
        float4 a = __ldcs(rA + lane + (i << 5));
        float4 b = __ldcs(rB + lane + (i << 5));
        int mb = (lane + (i << 5)) << 2;
        capture4(a, mb, TAU0, lmask, cbA, cntA);
        capture4(b, mb, TAU0, lmask, cbB, cntB);
    }
    __syncwarp();

    select10(cbA, cntA, lane, lmask, rA, g_idx + (size_t)rowbase * KK);
    select10(cbB, cntB, lane, lmask, rB, g_idx + (size_t)(rowbase + 1) * KK);
}

// ---------------- gather: one warp per (p,n), barrier-free ----------------
__global__ __launch_bounds__(256) void gather_kernel(float* __restrict__ out)
{
    __shared__ float sc[8][32];
    __shared__ float smax[8][4];
    __shared__ float ssum[8][4];

    int tid = threadIdx.x;
    int w = tid >> 5, lane = tid & 31;
    int gw = blockIdx.x * 8 + w;          // 0..8191
    int p = gw >> 11, n = gw & (NN - 1);

    int sub = lane & 7, grp = lane >> 3;
    const float4* Qrow = (const float4*)g_Q + ((size_t)p * NN + n) * 32;
    float4 q4[4];
#pragma unroll
    for (int j = 0; j < 4; ++j) q4[j] = Qrow[sub + 8 * j];

    int myidx = 0;
    if (lane < 3 * KK) {
        int pr = p * 3 + lane / KK;
        myidx = g_idx[((size_t)pr * NN + n) * KK + (lane % KK)];
    }

#pragma unroll
    for (int it = 0; it < 8; ++it) {
        int t = it * 4 + grp;
        int tq = (t < 30) ? t : 29;
        int qm = tq / KK;
        int q = qm + (qm >= p ? 1 : 0);
        int m = __shfl_sync(0xffffffffu, myidx, t & 31);
        const float4* Kr = (const float4*)g_K + ((size_t)q * NN + m) * 32;
        float s = 0.f;
#pragma unroll
        for (int j = 0; j < 4; ++j) {
            float4 k4 = __ldg(Kr + sub + 8 * j);
            s += q4[j].x * k4.x + q4[j].y * k4.y + q4[j].z * k4.z + q4[j].w * k4.w;
        }
        s += __shfl_xor_sync(0xffffffffu, s, 1);
        s += __shfl_xor_sync(0xffffffffu, s, 2);
        s += __shfl_xor_sync(0xffffffffu, s, 4);
        if (sub == 0 && t < 30) sc[w][t] = s * 0.08838834764831845f;
    }
    __syncwarp();

    if (lane < 3) {
        float mx = -3.4e38f;
#pragma unroll
        for (int k = 0; k < KK; ++k) mx = fmaxf(mx, sc[w][lane * KK + k]);
        smax[w][lane] = mx;
    }
    __syncwarp();
    if (lane < 3 * KK) sc[w][lane] = expf(sc[w][lane] - smax[w][lane / KK]);
    __syncwarp();
    if (lane < 3) {
        float su = 0.f;
#pragma unroll
        for (int k = 0; k < KK; ++k) su += sc[w][lane * KK + k];
        ssum[w][lane] = su;
    }
    __syncwarp();
    float wt = (lane < 3 * KK) ? sc[w][lane] / ssum[w][lane / KK] : 0.f;

    float4 mv = g_meanV4[p * 32 + lane];
    const float inv = 1.0f / NN;
    float4 acc = make_float4(mv.x * inv, mv.y * inv, mv.z * inv, mv.w * inv);
#pragma unroll
    for (int t = 0; t < 3 * KK; ++t) {
        float wb = __shfl_sync(0xffffffffu, wt, t);
        int   mb = __shfl_sync(0xffffffffu, myidx, t);
        int qm = t / KK;
        int q = qm + (qm >= p ? 1 : 0);
        float4 v4 = __ldg((const float4*)g_V + ((size_t)q * NN + mb) * 32 + lane);
        acc.x += wb * v4.x; acc.y += wb * v4.y;
        acc.z += wb * v4.z; acc.w += wb * v4.w;
    }
    ((float4*)out)[((size_t)p * NN + n) * 32 + lane] = acc;
}

// ---------------- launch ----------------
extern "C" void kernel_launch(void* const* d_in, const int* in_sizes, int n_in,
                              void* d_out, int out_size)
{
    const float* aligned = (const float*)d_in[0];
    const float* C       = (const float*)d_in[1];
    const float* WQ      = (const float*)d_in[2];
    const float* WK      = (const float*)d_in[3];
    const float* WV      = (const float*)d_in[4];
    float* out = (float*)d_out;

    void* meanp = nullptr;
    cudaGetSymbolAddress(&meanp, g_meanV4);

    cudaMemsetAsync(meanp, 0, VV * DD * sizeof(float));
    proj_topk_kernel<<<TOTAL_BLOCKS, 256>>>(aligned, WQ, WK, WV, C);
    gather_kernel<<<NN * VV / 8, 256>>>(out);
}

// round 14
// speedup vs baseline: 1.6030x; 1.0474x over previous
#include <cuda_runtime.h>
#include <math.h>

#define VV 4
#define NN 2048
#define DD 128
#define KK 10
#define NPAIR 12
#define TAU0 0.99f         // static threshold; exact fallback covers any input
#define PROJ_BLOCKS 384    // 12 mats x 32 tiles (64 rows)
#define TOPK_BLOCKS 1536   // 16 rows per block (8 warps x 2 rows)
#define TOTAL_BLOCKS (PROJ_BLOCKS + TOPK_BLOCKS)   // 1920, bid%5==0 -> proj

// ---------------- scratch (no allocs allowed) ----------------
__device__ float g_Q[VV * NN * DD];
__device__ float g_K[VV * NN * DD];
__device__ float g_V[VV * NN * DD];
__device__ int   g_idx[NPAIR * NN * KK];
__device__ float4 g_meanV4[VV * (DD / 4)];

// total-order 64-bit key: higher value wins; ties -> lower index (matches
// lax.top_k). C >= 0 so monotonic float map is bits | signbit.
__device__ __forceinline__ unsigned long long tk_key(float x, int m)
{
    unsigned int mb = __float_as_uint(x) | 0x80000000u;
    return ((unsigned long long)mb << 32) | (unsigned int)(NN - 1 - m);
}

__device__ __forceinline__ unsigned long long wmax64(unsigned long long k)
{
#pragma unroll
    for (int off = 16; off > 0; off >>= 1) {
        unsigned long long o = __shfl_xor_sync(0xffffffffu, k, off);
        if (o > k) k = o;
    }
    return k;
}

struct ProjS {
    float Xs[64][16];
    float Ws[16][132];
};
struct TopkS {
    unsigned long long cbuf[8][2][32];   // 4 KB
};

// exact fallback (rare: ~1.5% of rows): 10 bounded-rescan extraction rounds
// over the (L2-resident) global row. Emits the exact jax top-k SET.
__device__ void topk_fallback(const float4* __restrict__ rp4, int lane, int* outp)
{
    unsigned long long bound = ~0ull;
    for (int r = 0; r < KK; ++r) {
        unsigned long long cand = 0ull;
        for (int i = 0; i < 16; ++i) {
            float4 v = __ldg(rp4 + lane + (i << 5));
            int mb = (lane + (i << 5)) << 2;
            unsigned long long k;
            k = tk_key(v.x, mb + 0); if (k < bound && k > cand) cand = k;
            k = tk_key(v.y, mb + 1); if (k < bound && k > cand) cand = k;
            k = tk_key(v.z, mb + 2); if (k < bound && k > cand) cand = k;
            k = tk_key(v.w, mb + 3); if (k < bound && k > cand) cand = k;
        }
        unsigned long long m = wmax64(cand);
        if (lane == 0) outp[r] = NN - 1 - (int)(m & 0xffffffffu);
        bound = m;
    }
}

// branchless 4-bit hit nibble for one float4 (no warp sync)
__device__ __forceinline__ unsigned long long pack4(float4 a, int i)
{
    unsigned int m = (unsigned int)(a.x >= TAU0)
                   | ((unsigned int)(a.y >= TAU0) << 1)
                   | ((unsigned int)(a.z >= TAU0) << 2)
                   | ((unsigned int)(a.w >= TAU0) << 3);
    return (unsigned long long)m << (i * 4);
}

// rank-based select over <=32 candidates (no shfl dependency chains)
__device__ __forceinline__ void select10(
    const unsigned long long* cbuf, int cnt, int lane,
    unsigned int lmask, const float4* grow, int* outp)
{
    if (cnt >= KK && cnt <= 32) {
        unsigned long long mykey = (lane < cnt) ? cbuf[lane] : 0ull;
        int rank = 0;
#pragma unroll
        for (int j = 0; j < 32; ++j) {
            unsigned long long kj = __shfl_sync(0xffffffffu, mykey, j);
            rank += (kj > mykey);
        }
        bool in10 = (lane < cnt) && (rank < KK);   // keys unique -> exactly 10
        unsigned int m10 = __ballot_sync(0xffffffffu, in10);
        if (in10) {
            int pos = __popc(m10 & lmask);
            outp[pos] = NN - 1 - (int)(mykey & 0xffffffffu);
        }
    } else {
        topk_fallback(grow, lane, outp);
    }
}

// ================= fused proj (+meanV) + topk =================
__global__ __launch_bounds__(256, 3) void proj_topk_kernel(
    const float* __restrict__ aligned,
    const float* __restrict__ WQ,
    const float* __restrict__ WK,
    const float* __restrict__ WV,
    const float* __restrict__ C)
{
    __shared__ __align__(16) unsigned char smem_raw[sizeof(ProjS) > sizeof(TopkS)
                                                    ? sizeof(ProjS) : sizeof(TopkS)];
    int bid = blockIdx.x;
    int tid = threadIdx.x;
    int warp = tid >> 5, lane = tid & 31;

    if (bid % 5 == 0) {
        // ---------------- projection GEMM: 64 rows x 128 cols ----------------
        ProjS& S = *reinterpret_cast<ProjS*>(smem_raw);
        int pb = bid / 5;                 // 0..383
        int tile = pb & 31;
        int vm   = pb >> 5;               // 0..11
        int v = vm / 3, mat = vm % 3;
        const float* W = (mat == 0 ? WQ : (mat == 1 ? WK : WV)) + (size_t)v * DD * DD;
        float* Out = (mat == 0 ? g_Q : (mat == 1 ? g_K : g_V))
                     + (size_t)v * NN * DD + (size_t)tile * 64 * DD;
        const float* X = aligned + (size_t)v * NN * DD + (size_t)tile * 64 * DD;

        float acc[8][4];
#pragma unroll
        for (int i = 0; i < 8; ++i)
#pragma unroll
            for (int c = 0; c < 4; ++c) acc[i][c] = 0.f;

        for (int d0 = 0; d0 < DD; d0 += 16) {
            {
                int r = tid >> 2, f = tid & 3;
                float4 xv = *(const float4*)(X + (size_t)r * DD + d0 + f * 4);
                *(float4*)&S.Xs[r][f * 4] = xv;
            }
#pragma unroll
            for (int j = 0; j < 2; ++j) {
                int lin = tid * 2 + j;
                int e = lin >> 2, f = lin & 3;
                float4 wv = *(const float4*)(W + (size_t)e * DD + d0 + f * 4);
                S.Ws[f * 4 + 0][e] = wv.x;
                S.Ws[f * 4 + 1][e] = wv.y;
                S.Ws[f * 4 + 2][e] = wv.z;
                S.Ws[f * 4 + 3][e] = wv.w;
            }
            __syncthreads();
#pragma unroll
            for (int dd = 0; dd < 16; ++dd) {
                float4 b = *(const float4*)&S.Ws[dd][lane * 4];
#pragma unroll
                for (int i = 0; i < 8; ++i) {
                    float a = S.Xs[warp * 8 + i][dd];
                    acc[i][0] += a * b.x;
                    acc[i][1] += a * b.y;
                    acc[i][2] += a * b.z;
                    acc[i][3] += a * b.w;
                }
            }
            __syncthreads();
        }
#pragma unroll
        for (int i = 0; i < 8; ++i) {
            float4 o = make_float4(acc[i][0], acc[i][1], acc[i][2], acc[i][3]);
            *(float4*)(Out + (size_t)(warp * 8 + i) * DD + lane * 4) = o;
        }
        if (mat == 2) {
            // fused meanV: per-thread column partials over this tile's 8 rows
#pragma unroll
            for (int c = 0; c < 4; ++c) {
                float s = 0.f;
#pragma unroll
                for (int i = 0; i < 8; ++i) s += acc[i][c];
                atomicAdd((float*)&g_meanV4[0] + v * DD + lane * 4 + c, s);
            }
        }
        return;
    }

    // --- topk: 8 warps x 2 rows, sync-free mask capture + streaming LDG ---
    TopkS& S = *reinterpret_cast<TopkS*>(smem_raw);
    int tb = bid - bid / 5 - 1;           // 0..1535
    int rowbase = tb * 16 + warp * 2;     // rows rowbase, rowbase+1 (same pair)
    int pair = rowbase / NN, n0 = rowbase % NN;
    int p = pair / 3, qm = pair % 3;
    int q = qm + (qm >= p ? 1 : 0);
    const float4* rA = (const float4*)
        (C + (((size_t)p * VV + q) * NN + n0) * (size_t)NN);
    const float4* rB = rA + (NN / 4);

    // stream both rows, building per-lane hit masks — zero warp syncs,
    // so loads can run arbitrarily far ahead of the ALU
    unsigned long long hmA = 0ull, hmB = 0ull;
#pragma unroll
    for (int i = 0; i < 16; ++i) {
        float4 a = __ldcs(rA + lane + (i << 5));
        float4 b = __ldcs(rB + lane + (i << 5));
        hmA |= pack4(a, i);
        hmB |= pack4(b, i);
    }

    int cA = __popcll(hmA), cB = __popcll(hmB);

    // joint 5-step inclusive prefix scan for both rows
    int vA = cA, vB = cB;
#pragma unroll
    for (int off = 1; off < 32; off <<= 1) {
        int tA = __shfl_up_sync(0xffffffffu, vA, off);
        int tB = __shfl_up_sync(0xffffffffu, vB, off);
        if (lane >= off) { vA += tA; vB += tB; }
    }
    int offA = vA - cA, offB = vB - cB;
    int totA = __shfl_sync(0xffffffffu, vA, 31);
    int totB = __shfl_sync(0xffffffffu, vB, 31);

    unsigned int lmask = (1u << lane) - 1u;
    unsigned long long* cbA = &S.cbuf[warp][0][0];
    unsigned long long* cbB = &S.cbuf[warp][1][0];
    const float* fA = (const float*)rA;
    const float* fB = (const float*)rB;

    // each lane writes its own hits (E ~0.64/lane); value re-read hits L2
    while (hmA) {
        int b = __ffsll(hmA) - 1; hmA &= hmA - 1;
        int m = ((lane + ((b >> 2) << 5)) << 2) + (b & 3);
        if (offA < 32) cbA[offA] = tk_key(__ldg(fA + m), m);
        offA++;
    }
    while (hmB) {
        int b = __ffsll(hmB) - 1; hmB &= hmB - 1;
        int m = ((lane + ((b >> 2) << 5)) << 2) + (b & 3);
        if (offB < 32) cbB[offB] = tk_key(__ldg(fB + m), m);
        offB++;
    }
    __syncwarp();

    select10(cbA, totA, lane, lmask, rA, g_idx + (size_t)rowbase * KK);
    select10(cbB, totB, lane, lmask, rB, g_idx + (size_t)(rowbase + 1) * KK);
}

// tiny aux kernel: shifts launch ordering so ncu (-s5 -c1) profiles proj_topk
__global__ void aux_kernel() {}

// ---------------- gather: one warp per (p,n), barrier-free ----------------
__global__ __launch_bounds__(256) void gather_kernel(float* __restrict__ out)
{
    __shared__ float sc[8][32];
    __shared__ float smax[8][4];
    __shared__ float ssum[8][4];

    int tid = threadIdx.x;
    int w = tid >> 5, lane = tid & 31;
    int gw = blockIdx.x * 8 + w;          // 0..8191
    int p = gw >> 11, n = gw & (NN - 1);

    int sub = lane & 7, grp = lane >> 3;
    const float4* Qrow = (const float4*)g_Q + ((size_t)p * NN + n) * 32;
    float4 q4[4];
#pragma unroll
    for (int j = 0; j < 4; ++j) q4[j] = Qrow[sub + 8 * j];

    int myidx = 0;
    if (lane < 3 * KK) {
        int pr = p * 3 + lane / KK;
        myidx = g_idx[((size_t)pr * NN + n) * KK + (lane % KK)];
    }

#pragma unroll
    for (int it = 0; it < 8; ++it) {
        int t = it * 4 + grp;
        int tq = (t < 30) ? t : 29;
        int qm = tq / KK;
        int q = qm + (qm >= p ? 1 : 0);
        int m = __shfl_sync(0xffffffffu, myidx, t & 31);
        const float4* Kr = (const float4*)g_K + ((size_t)q * NN + m) * 32;
        float s = 0.f;
#pragma unroll
        for (int j = 0; j < 4; ++j) {
            float4 k4 = __ldg(Kr + sub + 8 * j);
            s += q4[j].x * k4.x + q4[j].y * k4.y + q4[j].z * k4.z + q4[j].w * k4.w;
        }
        s += __shfl_xor_sync(0xffffffffu, s, 1);
        s += __shfl_xor_sync(0xffffffffu, s, 2);
        s += __shfl_xor_sync(0xffffffffu, s, 4);
        if (sub == 0 && t < 30) sc[w][t] = s * 0.08838834764831845f;
    }
    __syncwarp();

    if (lane < 3) {
        float mx = -3.4e38f;
#pragma unroll
        for (int k = 0; k < KK; ++k) mx = fmaxf(mx, sc[w][lane * KK + k]);
        smax[w][lane] = mx;
    }
    __syncwarp();
    if (lane < 3 * KK) sc[w][lane] = expf(sc[w][lane] - smax[w][lane / KK]);
    __syncwarp();
    if (lane < 3) {
        float su = 0.f;
#pragma unroll
        for (int k = 0; k < KK; ++k) su += sc[w][lane * KK + k];
        ssum[w][lane] = su;
    }
    __syncwarp();
    float wt = (lane < 3 * KK) ? sc[w][lane] / ssum[w][lane / KK] : 0.f;

    float4 mv = g_meanV4[p * 32 + lane];
    const float inv = 1.0f / NN;
    float4 acc = make_float4(mv.x * inv, mv.y * inv, mv.z * inv, mv.w * inv);
#pragma unroll
    for (int t = 0; t < 3 * KK; ++t) {
        float wb = __shfl_sync(0xffffffffu, wt, t);
        int   mb = __shfl_sync(0xffffffffu, myidx, t);
        int qm = t / KK;
        int q = qm + (qm >= p ? 1 : 0);
        float4 v4 = __ldg((const float4*)g_V + ((size_t)q * NN + mb) * 32 + lane);
        acc.x += wb * v4.x; acc.y += wb * v4.y;
        acc.z += wb * v4.z; acc.w += wb * v4.w;
    }
    ((float4*)out)[((size_t)p * NN + n) * 32 + lane] = acc;
}

// ---------------- launch ----------------
extern "C" void kernel_launch(void* const* d_in, const int* in_sizes, int n_in,
                              void* d_out, int out_size)
{
    const float* aligned = (const float*)d_in[0];
    const float* C       = (const float*)d_in[1];
    const float* WQ      = (const float*)d_in[2];
    const float* WK      = (const float*)d_in[3];
    const float* WV      = (const float*)d_in[4];
    float* out = (float*)d_out;

    void* meanp = nullptr;
    cudaGetSymbolAddress(&meanp, g_meanV4);

    cudaMemsetAsync(meanp, 0, VV * DD * sizeof(float));     // launch 0
    proj_topk_kernel<<<TOTAL_BLOCKS, 256>>>(aligned, WQ, WK, WV, C);  // launch 1
    aux_kernel<<<1, 32>>>();                                // launch 2
    gather_kernel<<<NN * VV / 8, 256>>>(out);               // launch 3
}

// round 15
// speedup vs baseline: 1.6493x; 1.0289x over previous
#include <cuda_runtime.h>
#include <math.h>

#define VV 4
#define NN 2048
#define DD 128
#define KK 10
#define NPAIR 12
#define TAU0 0.99f         // static threshold; exact fallback covers any input
#define PROJ_BLOCKS 384    // 12 mats x 32 tiles (64 rows)
#define TOPK_BLOCKS 1536   // 16 rows per block (8 warps x 2 rows)
#define TOTAL_BLOCKS (PROJ_BLOCKS + TOPK_BLOCKS)   // 1920, bid%5==0 -> proj

// ---------------- scratch (no allocs allowed) ----------------
__device__ float g_Q[VV * NN * DD];
__device__ float g_K[VV * NN * DD];
__device__ float g_V[VV * NN * DD];
__device__ int   g_idx[NPAIR * NN * KK];
__device__ float4 g_meanV4[VV * (DD / 4)];

// total-order 64-bit key: higher value wins; ties -> lower index (matches
// lax.top_k). C >= 0 so monotonic float map is bits | signbit.
__device__ __forceinline__ unsigned long long tk_key(float x, int m)
{
    unsigned int mb = __float_as_uint(x) | 0x80000000u;
    return ((unsigned long long)mb << 32) | (unsigned int)(NN - 1 - m);
}

__device__ __forceinline__ unsigned long long wmax64(unsigned long long k)
{
#pragma unroll
    for (int off = 16; off > 0; off >>= 1) {
        unsigned long long o = __shfl_xor_sync(0xffffffffu, k, off);
        if (o > k) k = o;
    }
    return k;
}

struct ProjS {
    float Xs[16][66];    // [dd][row], 66-pad keeps 8B alignment for pair loads
    float Ws[16][132];
};
struct TopkS {
    unsigned long long cbuf[8][2][32];   // 4 KB
};

// exact fallback (rare: ~1.5% of rows): 10 bounded-rescan extraction rounds
// over the (L2-resident) global row. Emits the exact jax top-k SET.
__device__ void topk_fallback(const float4* __restrict__ rp4, int lane, int* outp)
{
    unsigned long long bound = ~0ull;
    for (int r = 0; r < KK; ++r) {
        unsigned long long cand = 0ull;
        for (int i = 0; i < 16; ++i) {
            float4 v = __ldg(rp4 + lane + (i << 5));
            int mb = (lane + (i << 5)) << 2;
            unsigned long long k;
            k = tk_key(v.x, mb + 0); if (k < bound && k > cand) cand = k;
            k = tk_key(v.y, mb + 1); if (k < bound && k > cand) cand = k;
            k = tk_key(v.z, mb + 2); if (k < bound && k > cand) cand = k;
            k = tk_key(v.w, mb + 3); if (k < bound && k > cand) cand = k;
        }
        unsigned long long m = wmax64(cand);
        if (lane == 0) outp[r] = NN - 1 - (int)(m & 0xffffffffu);
        bound = m;
    }
}

// branchless 4-bit hit nibble for one float4 (no warp sync)
__device__ __forceinline__ unsigned long long pack4(float4 a, int i)
{
    unsigned int m = (unsigned int)(a.x >= TAU0)
                   | ((unsigned int)(a.y >= TAU0) << 1)
                   | ((unsigned int)(a.z >= TAU0) << 2)
                   | ((unsigned int)(a.w >= TAU0) << 3);
    return (unsigned long long)m << (i * 4);
}

// rank-based select over <=32 candidates (no shfl dependency chains)
__device__ __forceinline__ void select10(
    const unsigned long long* cbuf, int cnt, int lane,
    unsigned int lmask, const float4* grow, int* outp)
{
    if (cnt >= KK && cnt <= 32) {
        unsigned long long mykey = (lane < cnt) ? cbuf[lane] : 0ull;
        int rank = 0;
#pragma unroll
        for (int j = 0; j < 32; ++j) {
            unsigned long long kj = __shfl_sync(0xffffffffu, mykey, j);
            rank += (kj > mykey);
        }
        bool in10 = (lane < cnt) && (rank < KK);   // keys unique -> exactly 10
        unsigned int m10 = __ballot_sync(0xffffffffu, in10);
        if (in10) {
            int pos = __popc(m10 & lmask);
            outp[pos] = NN - 1 - (int)(mykey & 0xffffffffu);
        }
    } else {
        topk_fallback(grow, lane, outp);
    }
}

// packed f32x2 FMA (sm_103a FFMA2): acc += a2 * b2, componentwise fp32,
// identical rounding to scalar FFMA
__device__ __forceinline__ void ffma2(unsigned long long& acc,
                                      unsigned long long a2,
                                      unsigned long long b2)
{
    asm("fma.rn.f32x2 %0, %1, %2, %0;" : "+l"(acc) : "l"(a2), "l"(b2));
}

__device__ __forceinline__ unsigned long long pack_ff(float lo, float hi)
{
    unsigned long long r;
    asm("mov.b64 %0, {%1, %2};" : "=l"(r) : "r"(__float_as_uint(lo)),
                                            "r"(__float_as_uint(hi)));
    return r;
}

__device__ __forceinline__ float f2_lo(unsigned long long v)
{ return __uint_as_float((unsigned int)v); }
__device__ __forceinline__ float f2_hi(unsigned long long v)
{ return __uint_as_float((unsigned int)(v >> 32)); }

// ================= fused proj (+meanV) + topk =================
__global__ __launch_bounds__(256, 3) void proj_topk_kernel(
    const float* __restrict__ aligned,
    const float* __restrict__ WQ,
    const float* __restrict__ WK,
    const float* __restrict__ WV,
    const float* __restrict__ C)
{
    __shared__ __align__(16) unsigned char smem_raw[sizeof(ProjS) > sizeof(TopkS)
                                                    ? sizeof(ProjS) : sizeof(TopkS)];
    int bid = blockIdx.x;
    int tid = threadIdx.x;
    int warp = tid >> 5, lane = tid & 31;

    if (bid % 5 == 0) {
        // ------- projection GEMM: 64 rows x 128 cols, packed f32x2 FMA -------
        ProjS& S = *reinterpret_cast<ProjS*>(smem_raw);
        int pb = bid / 5;                 // 0..383
        int tile = pb & 31;
        int vm   = pb >> 5;               // 0..11
        int v = vm / 3, mat = vm % 3;
        const float* W = (mat == 0 ? WQ : (mat == 1 ? WK : WV)) + (size_t)v * DD * DD;
        float* Out = (mat == 0 ? g_Q : (mat == 1 ? g_K : g_V))
                     + (size_t)v * NN * DD + (size_t)tile * 64 * DD;
        const float* X = aligned + (size_t)v * NN * DD + (size_t)tile * 64 * DD;

        // acc2[pi][c]: rows (warp*8+2pi, warp*8+2pi+1), col lane*4+c
        unsigned long long acc2[4][4];
#pragma unroll
        for (int i = 0; i < 4; ++i)
#pragma unroll
            for (int c = 0; c < 4; ++c) acc2[i][c] = 0ull;

        for (int d0 = 0; d0 < DD; d0 += 16) {
            {
                // X tile 64x16 -> transposed store Xs[dd][row]
                int r = tid >> 2, f = tid & 3;
                float4 xv = *(const float4*)(X + (size_t)r * DD + d0 + f * 4);
                S.Xs[f * 4 + 0][r] = xv.x;
                S.Xs[f * 4 + 1][r] = xv.y;
                S.Xs[f * 4 + 2][r] = xv.z;
                S.Xs[f * 4 + 3][r] = xv.w;
            }
#pragma unroll
            for (int j = 0; j < 2; ++j) {
                int lin = tid * 2 + j;
                int e = lin >> 2, f = lin & 3;
                float4 wv = *(const float4*)(W + (size_t)e * DD + d0 + f * 4);
                S.Ws[f * 4 + 0][e] = wv.x;
                S.Ws[f * 4 + 1][e] = wv.y;
                S.Ws[f * 4 + 2][e] = wv.z;
                S.Ws[f * 4 + 3][e] = wv.w;
            }
            __syncthreads();
#pragma unroll
            for (int dd = 0; dd < 16; ++dd) {
                float4 b = *(const float4*)&S.Ws[dd][lane * 4];
                unsigned long long b2[4] = {
                    pack_ff(b.x, b.x), pack_ff(b.y, b.y),
                    pack_ff(b.z, b.z), pack_ff(b.w, b.w) };
                // warp-uniform 8B broadcast loads of row pairs
                const unsigned long long* ap =
                    (const unsigned long long*)&S.Xs[dd][warp * 8];
#pragma unroll
                for (int i = 0; i < 4; ++i) {
                    unsigned long long a2 = ap[i];
                    ffma2(acc2[i][0], a2, b2[0]);
                    ffma2(acc2[i][1], a2, b2[1]);
                    ffma2(acc2[i][2], a2, b2[2]);
                    ffma2(acc2[i][3], a2, b2[3]);
                }
            }
            __syncthreads();
        }
#pragma unroll
        for (int i = 0; i < 4; ++i) {
            float4 o0 = make_float4(f2_lo(acc2[i][0]), f2_lo(acc2[i][1]),
                                    f2_lo(acc2[i][2]), f2_lo(acc2[i][3]));
            float4 o1 = make_float4(f2_hi(acc2[i][0]), f2_hi(acc2[i][1]),
                                    f2_hi(acc2[i][2]), f2_hi(acc2[i][3]));
            *(float4*)(Out + (size_t)(warp * 8 + 2 * i)     * DD + lane * 4) = o0;
            *(float4*)(Out + (size_t)(warp * 8 + 2 * i + 1) * DD + lane * 4) = o1;
        }
        if (mat == 2) {
            // fused meanV: per-thread column partials over this tile's 8 rows
#pragma unroll
            for (int c = 0; c < 4; ++c) {
                float s = 0.f;
#pragma unroll
                for (int i = 0; i < 4; ++i)
                    s += f2_lo(acc2[i][c]) + f2_hi(acc2[i][c]);
                atomicAdd((float*)&g_meanV4[0] + v * DD + lane * 4 + c, s);
            }
        }
        return;
    }

    // --- topk: 8 warps x 2 rows, batched loads + sync-free mask capture ---
    TopkS& S = *reinterpret_cast<TopkS*>(smem_raw);
    int tb = bid - bid / 5 - 1;           // 0..1535
    int rowbase = tb * 16 + warp * 2;     // rows rowbase, rowbase+1 (same pair)
    int pair = rowbase / NN, n0 = rowbase % NN;
    int p = pair / 3, qm = pair % 3;
    int q = qm + (qm >= p ? 1 : 0);
    const float4* rA = (const float4*)
        (C + (((size_t)p * VV + q) * NN + n0) * (size_t)NN);
    const float4* rB = rA + (NN / 4);

    unsigned long long hmA = 0ull, hmB = 0ull;
#pragma unroll
    for (int ii = 0; ii < 4; ++ii) {
        float4 a[4], b[4];
        // 8 independent loads issued before ANY consumption -> MLP >= 8
#pragma unroll
        for (int j = 0; j < 4; ++j) {
            a[j] = __ldcs(rA + lane + ((ii * 4 + j) << 5));
            b[j] = __ldcs(rB + lane + ((ii * 4 + j) << 5));
        }
#pragma unroll
        for (int j = 0; j < 4; ++j) {
            hmA |= pack4(a[j], ii * 4 + j);
            hmB |= pack4(b[j], ii * 4 + j);
        }
    }

    int cA = __popcll(hmA), cB = __popcll(hmB);

    // joint 5-step inclusive prefix scan for both rows
    int vA = cA, vB = cB;
#pragma unroll
    for (int off = 1; off < 32; off <<= 1) {
        int tA = __shfl_up_sync(0xffffffffu, vA, off);
        int tB = __shfl_up_sync(0xffffffffu, vB, off);
        if (lane >= off) { vA += tA; vB += tB; }
    }
    int offA = vA - cA, offB = vB - cB;
    int totA = __shfl_sync(0xffffffffu, vA, 31);
    int totB = __shfl_sync(0xffffffffu, vB, 31);

    unsigned int lmask = (1u << lane) - 1u;
    unsigned long long* cbA = &S.cbuf[warp][0][0];
    unsigned long long* cbB = &S.cbuf[warp][1][0];
    const float* fA = (const float*)rA;
    const float* fB = (const float*)rB;

    // each lane writes its own hits (E ~0.64/lane); value re-read hits L2
    while (hmA) {
        int b = __ffsll(hmA) - 1; hmA &= hmA - 1;
        int m = ((lane + ((b >> 2) << 5)) << 2) + (b & 3);
        if (offA < 32) cbA[offA] = tk_key(__ldg(fA + m), m);
        offA++;
    }
    while (hmB) {
        int b = __ffsll(hmB) - 1; hmB &= hmB - 1;
        int m = ((lane + ((b >> 2) << 5)) << 2) + (b & 3);
        if (offB < 32) cbB[offB] = tk_key(__ldg(fB + m), m);
        offB++;
    }
    __syncwarp();

    select10(cbA, totA, lane, lmask, rA, g_idx + (size_t)rowbase * KK);
    select10(cbB, totB, lane, lmask, rB, g_idx + (size_t)(rowbase + 1) * KK);
}

// tiny aux kernel: shifts launch ordering so ncu (-s5 -c1) profiles proj_topk
__global__ void aux_kernel() {}

// ---------------- gather: one warp per (p,n), barrier-free ----------------
__global__ __launch_bounds__(256) void gather_kernel(float* __restrict__ out)
{
    __shared__ float sc[8][32];
    __shared__ float smax[8][4];
    __shared__ float ssum[8][4];

    int tid = threadIdx.x;
    int w = tid >> 5, lane = tid & 31;
    int gw = blockIdx.x * 8 + w;          // 0..8191
    int p = gw >> 11, n = gw & (NN - 1);

    int sub = lane & 7, grp = lane >> 3;
    const float4* Qrow = (const float4*)g_Q + ((size_t)p * NN + n) * 32;
    float4 q4[4];
#pragma unroll
    for (int j = 0; j < 4; ++j) q4[j] = Qrow[sub + 8 * j];

    int myidx = 0;
    if (lane < 3 * KK) {
        int pr = p * 3 + lane / KK;
        myidx = g_idx[((size_t)pr * NN + n) * KK + (lane % KK)];
    }

#pragma unroll
    for (int it = 0; it < 8; ++it) {
        int t = it * 4 + grp;
        int tq = (t < 30) ? t : 29;
        int qm = tq / KK;
        int q = qm + (qm >= p ? 1 : 0);
        int m = __shfl_sync(0xffffffffu, myidx, t & 31);
        const float4* Kr = (const float4*)g_K + ((size_t)q * NN + m) * 32;
        float s = 0.f;
#pragma unroll
        for (int j = 0; j < 4; ++j) {
            float4 k4 = __ldg(Kr + sub + 8 * j);
            s += q4[j].x * k4.x + q4[j].y * k4.y + q4[j].z * k4.z + q4[j].w * k4.w;
        }
        s += __shfl_xor_sync(0xffffffffu, s, 1);
        s += __shfl_xor_sync(0xffffffffu, s, 2);
        s += __shfl_xor_sync(0xffffffffu, s, 4);
        if (sub == 0 && t < 30) sc[w][t] = s * 0.08838834764831845f;
    }
    __syncwarp();

    if (lane < 3) {
        float mx = -3.4e38f;
#pragma unroll
        for (int k = 0; k < KK; ++k) mx = fmaxf(mx, sc[w][lane * KK + k]);
        smax[w][lane] = mx;
    }
    __syncwarp();
    if (lane < 3 * KK) sc[w][lane] = expf(sc[w][lane] - smax[w][lane / KK]);
    __syncwarp();
    if (lane < 3) {
        float su = 0.f;
#pragma unroll
        for (int k = 0; k < KK; ++k) su += sc[w][lane * KK + k];
        ssum[w][lane] = su;
    }
    __syncwarp();
    float wt = (lane < 3 * KK) ? sc[w][lane] / ssum[w][lane / KK] : 0.f;

    float4 mv = g_meanV4[p * 32 + lane];
    const float inv = 1.0f / NN;
    float4 acc = make_float4(mv.x * inv, mv.y * inv, mv.z * inv, mv.w * inv);
#pragma unroll
    for (int t = 0; t < 3 * KK; ++t) {
        float wb = __shfl_sync(0xffffffffu, wt, t);
        int   mb = __shfl_sync(0xffffffffu, myidx, t);
        int qm = t / KK;
        int q = qm + (qm >= p ? 1 : 0);
        float4 v4 = __ldg((const float4*)g_V + ((size_t)q * NN + mb) * 32 + lane);
        acc.x += wb * v4.x; acc.y += wb * v4.y;
        acc.z += wb * v4.z; acc.w += wb * v4.w;
    }
    ((float4*)out)[((size_t)p * NN + n) * 32 + lane] = acc;
}

// ---------------- launch ----------------
extern "C" void kernel_launch(void* const* d_in, const int* in_sizes, int n_in,
                              void* d_out, int out_size)
{
    const float* aligned = (const float*)d_in[0];
    const float* C       = (const float*)d_in[1];
    const float* WQ      = (const float*)d_in[2];
    const float* WK      = (const float*)d_in[3];
    const float* WV      = (const float*)d_in[4];
    float* out = (float*)d_out;

    void* meanp = nullptr;
    cudaGetSymbolAddress(&meanp, g_meanV4);

    cudaMemsetAsync(meanp, 0, VV * DD * sizeof(float));     // launch 0
    proj_topk_kernel<<<TOTAL_BLOCKS, 256>>>(aligned, WQ, WK, WV, C);  // launch 1
    aux_kernel<<<1, 32>>>();                                // launch 2
    gather_kernel<<<NN * VV / 8, 256>>>(out);               // launch 3
}